// round 1
// baseline (speedup 1.0000x reference)
#include <cuda_runtime.h>
#include <cstdint>

// Problem constants (fixed by setup_inputs)
#define BH      64      // leading dim of q/k/v (= 4 batch * 16 heads)
#define NH      16      // heads (for W indexing: h = bh & 15)
#define NBUCK   32      // buckets
#define BSZ     128     // bucket size (tokens per bucket)
#define DIM     64      // head dim
#define TOK     4096    // tokens per row
#define ROW     (TOK*DIM)        // 262144 floats per bh row
#define BUCKF   (BSZ*DIM)        // 8192 floats per bucket tile

// Scratch (static device arrays; no runtime allocation allowed)
__device__ float g_pl[BH*NBUCK*DIM];        // bucket sums of K
__device__ float g_R [BH*NBUCK*NBUCK];      // sinkhorn routing matrices exp(R)
__device__ float g_kmix[BH*TOK*DIM];        // mixed K

// ---------------------------------------------------------------------------
// K1: pl[bh][i][d] = sum_s k[bh][i*128+s][d]
// ---------------------------------------------------------------------------
__global__ void k_bucket_sum(const float* __restrict__ k) {
    int bid = blockIdx.x;               // 2048 = BH*NBUCK
    int bh = bid >> 5, i = bid & 31, d = threadIdx.x;   // 64 threads
    const float* kb = k + (size_t)bh*ROW + (size_t)i*BUCKF;
    float s = 0.f;
    #pragma unroll 8
    for (int ss = 0; ss < BSZ; ss++) s += kb[ss*DIM + d];
    g_pl[(bh*NBUCK + i)*DIM + d] = s;
}

// ---------------------------------------------------------------------------
// JAX threefry2x32 (partitionable mode, key = jax.random.key(42) -> (0,42)):
// bits[n] = o0 ^ o1 where (o0,o1) = threefry2x32((0,42), (hi=0, lo=n))
// ---------------------------------------------------------------------------
__device__ __forceinline__ uint32_t rotl32(uint32_t x, int r) {
    return (x << r) | (x >> (32 - r));
}
__device__ __forceinline__ uint32_t jax_bits32(uint32_t n) {
    const uint32_t k0 = 0u, k1 = 42u, k2 = 0u ^ 42u ^ 0x1BD11BDAu;
    uint32_t x0 = k0;          // hi counter (0) + ks0
    uint32_t x1 = n + k1;      // lo counter + ks1
#define TF_R(r) { x0 += x1; x1 = rotl32(x1, r); x1 ^= x0; }
    TF_R(13) TF_R(15) TF_R(26) TF_R(6)   x0 += k1; x1 += k2 + 1u;
    TF_R(17) TF_R(29) TF_R(16) TF_R(24)  x0 += k2; x1 += k0 + 2u;
    TF_R(13) TF_R(15) TF_R(26) TF_R(6)   x0 += k0; x1 += k1 + 3u;
    TF_R(17) TF_R(29) TF_R(16) TF_R(24)  x0 += k1; x1 += k2 + 4u;
    TF_R(13) TF_R(15) TF_R(26) TF_R(6)   x0 += k2; x1 += k0 + 5u;
#undef TF_R
    return x0 ^ x1;
}

// ---------------------------------------------------------------------------
// K2: routing + gumbel + 5x sinkhorn + exp.  One block per bh, 1024 threads.
// thread (i = tid>>5, f = tid&31) owns R[i][f]; warp i == row i.
// ---------------------------------------------------------------------------
__global__ __launch_bounds__(1024) void k_route_sinkhorn(const float* __restrict__ Wk) {
    int bh = blockIdx.x;
    int h  = bh & (NH - 1);
    int tid = threadIdx.x;
    int i = tid >> 5, f = tid & 31;

    __shared__ float spl[NBUCK*DIM];   // [i][d]
    __shared__ float sW [DIM*NBUCK];   // [d][f]
    __shared__ float sM [NBUCK*33];    // padded matrix for column reductions

    spl[tid]        = g_pl[bh*(NBUCK*DIM) + tid];
    spl[tid + 1024] = g_pl[bh*(NBUCK*DIM) + tid + 1024];
    sW[tid]         = Wk[h*(DIM*NBUCK) + tid];
    sW[tid + 1024]  = Wk[h*(DIM*NBUCK) + tid + 1024];
    __syncthreads();

    float r = 0.f;
    #pragma unroll
    for (int d = 0; d < DIM; d++) r += spl[i*DIM + d] * sW[d*NBUCK + f];

    // gumbel noise, flat index over R[4,16,32,32]
    uint32_t n = (uint32_t)(bh*1024 + tid);
    uint32_t bits = jax_bits32(n);
    float u = __uint_as_float((bits >> 9) | 0x3f800000u) - 1.0f;
    float g = -logf(-logf(u + 1e-6f) + 1e-6f);
    r = (r + g) / 0.75f;

    for (int it = 0; it < 5; it++) {
        // rows (axis -1): within warp
        float m = r;
        #pragma unroll
        for (int o = 16; o >= 1; o >>= 1) m = fmaxf(m, __shfl_xor_sync(0xffffffffu, m, o));
        float s = expf(r - m);
        #pragma unroll
        for (int o = 16; o >= 1; o >>= 1) s += __shfl_xor_sync(0xffffffffu, s, o);
        r = r - (logf(s) + m);

        // cols (axis -2): via shared
        __syncthreads();
        sM[i*33 + f] = r;
        __syncthreads();
        float cm = -3.4e38f;
        #pragma unroll
        for (int ii = 0; ii < NBUCK; ii++) cm = fmaxf(cm, sM[ii*33 + f]);
        float cs = 0.f;
        #pragma unroll
        for (int ii = 0; ii < NBUCK; ii++) cs += expf(sM[ii*33 + f] - cm);
        r = r - (logf(cs) + cm);
    }
    g_R[bh*1024 + tid] = expf(r);
}

// ---------------------------------------------------------------------------
// K3: Kmix[bh][i][:] = sum_j (R[i][j] + I) * K[bh][j][:]
// block = (bh, 256-col chunk), 256 threads, 32 accumulators each.
// ---------------------------------------------------------------------------
__global__ __launch_bounds__(256) void k_kmix(const float* __restrict__ k) {
    int bid = blockIdx.x;               // 2048 = BH * 32 chunks
    int bh = bid >> 5, c = bid & 31;
    int tid = threadIdx.x;

    __shared__ float sA[NBUCK][NBUCK];
    for (int idx = tid; idx < NBUCK*NBUCK; idx += 256) {
        int ii = idx >> 5, jj = idx & 31;
        sA[ii][jj] = g_R[bh*1024 + idx] + ((ii == jj) ? 1.0f : 0.0f);
    }
    __syncthreads();

    const float* kb = k + (size_t)bh*ROW;
    int col = c*256 + tid;              // within [0, 8192)

    float acc[NBUCK];
    #pragma unroll
    for (int ii = 0; ii < NBUCK; ii++) acc[ii] = 0.f;

    #pragma unroll 4
    for (int j = 0; j < NBUCK; j++) {
        float val = kb[j*BUCKF + col];
        #pragma unroll
        for (int ii = 0; ii < NBUCK; ii++) acc[ii] += sA[ii][j] * val;
    }
    float* ob = g_kmix + (size_t)bh*ROW;
    #pragma unroll
    for (int ii = 0; ii < NBUCK; ii++) ob[ii*BUCKF + col] = acc[ii];
}

// ---------------------------------------------------------------------------
// K4: bucket attention. One block per bucket (2048), 256 threads.
//   QK^T (128x128) via 8x8 register tiles from transposed padded smem,
//   in-register softmax (shfl_xor over the 16 tx lanes), P@V from smem.
// Shared (dynamic, 100352 B):
//   phase1: sQT[64][132] @0, sKT[64][132] @8448    (ends at 16896)
//   phase2: sPT[128][132] @0 (aliases Q/K), sV[128][64] @16896
// ---------------------------------------------------------------------------
#define PAD 132
__global__ __launch_bounds__(256) void k_attn(const float* __restrict__ q,
                                              const float* __restrict__ v,
                                              float* __restrict__ out) {
    extern __shared__ float sm[];
    float* sQT = sm;
    float* sKT = sm + 64*PAD;
    float* sPT = sm;                 // phase 2 alias
    float* sV  = sm + 128*PAD;

    int bid = blockIdx.x;
    size_t base = (size_t)bid * BUCKF;
    const float* qb = q      + base;
    const float* kb = g_kmix + base;
    const float* vb = v      + base;
    float*       ob = out    + base;

    int tid = threadIdx.x;
    // cooperative transposed loads (pad 132 -> conflict-free STS)
    for (int idx = tid; idx < BUCKF; idx += 256) {
        int s = idx >> 6, d = idx & 63;
        sQT[d*PAD + s] = qb[idx];
        sKT[d*PAD + s] = kb[idx];
        sV[idx]        = vb[idx];
    }
    __syncthreads();

    int ty = tid >> 4, tx = tid & 15;
    int a0 = 4*ty, a1 = 64 + 4*ty;
    int b0 = 4*tx, b1 = 64 + 4*tx;

    float c[8][8];
    #pragma unroll
    for (int m = 0; m < 8; m++)
        #pragma unroll
        for (int n2 = 0; n2 < 8; n2++) c[m][n2] = 0.f;

    // ---- GEMM1: logits = Q K^T ----
    #pragma unroll 4
    for (int d = 0; d < DIM; d++) {
        const float* qd = sQT + d*PAD;
        const float* kd = sKT + d*PAD;
        float4 A0 = *(const float4*)(qd + a0);
        float4 A1 = *(const float4*)(qd + a1);
        float4 B0 = *(const float4*)(kd + b0);
        float4 B1 = *(const float4*)(kd + b1);
        float a[8] = {A0.x, A0.y, A0.z, A0.w, A1.x, A1.y, A1.z, A1.w};
        float b[8] = {B0.x, B0.y, B0.z, B0.w, B1.x, B1.y, B1.z, B1.w};
        #pragma unroll
        for (int m = 0; m < 8; m++)
            #pragma unroll
            for (int n2 = 0; n2 < 8; n2++) c[m][n2] += a[m] * b[n2];
    }

    // ---- softmax over cols (key dim), rows split across 16 tx lanes ----
    const float scale = 0.125f;   // 1/sqrt(64)
    #pragma unroll
    for (int m = 0; m < 8; m++) {
        float rm = -3.4e38f;
        #pragma unroll
        for (int n2 = 0; n2 < 8; n2++) { c[m][n2] *= scale; rm = fmaxf(rm, c[m][n2]); }
        #pragma unroll
        for (int o = 8; o >= 1; o >>= 1) rm = fmaxf(rm, __shfl_xor_sync(0xffffffffu, rm, o));
        float es = 0.f;
        #pragma unroll
        for (int n2 = 0; n2 < 8; n2++) { c[m][n2] = expf(c[m][n2] - rm); es += c[m][n2]; }
        #pragma unroll
        for (int o = 8; o >= 1; o >>= 1) es += __shfl_xor_sync(0xffffffffu, es, o);
        float inv = 1.0f / es;
        #pragma unroll
        for (int n2 = 0; n2 < 8; n2++) c[m][n2] *= inv;
    }

    __syncthreads();   // all reads of sQT/sKT complete before aliasing as sPT

    // store P transposed: sPT[j][s] = P[s][j]
    #pragma unroll
    for (int m = 0; m < 8; m++) {
        int row = (m < 4) ? (a0 + m) : (a1 + m - 4);
        #pragma unroll
        for (int n2 = 0; n2 < 8; n2++) {
            int colj = (n2 < 4) ? (b0 + n2) : (b1 + n2 - 4);
            sPT[colj*PAD + row] = c[m][n2];
        }
    }
    __syncthreads();

    // ---- GEMM2: out = P V ----
    float o[8][4];
    #pragma unroll
    for (int m = 0; m < 8; m++)
        #pragma unroll
        for (int n2 = 0; n2 < 4; n2++) o[m][n2] = 0.f;

    #pragma unroll 2
    for (int j = 0; j < BSZ; j++) {
        const float* pj = sPT + j*PAD;
        float4 A0 = *(const float4*)(pj + a0);
        float4 A1 = *(const float4*)(pj + a1);
        float4 B  = *(const float4*)(sV + j*DIM + b0);
        float a[8] = {A0.x, A0.y, A0.z, A0.w, A1.x, A1.y, A1.z, A1.w};
        float b[4] = {B.x, B.y, B.z, B.w};
        #pragma unroll
        for (int m = 0; m < 8; m++)
            #pragma unroll
            for (int n2 = 0; n2 < 4; n2++) o[m][n2] += a[m] * b[n2];
    }

    #pragma unroll
    for (int m = 0; m < 8; m++) {
        int row = (m < 4) ? (a0 + m) : (a1 + m - 4);
        *(float4*)(ob + row*DIM + b0) = make_float4(o[m][0], o[m][1], o[m][2], o[m][3]);
    }
}

// ---------------------------------------------------------------------------
extern "C" void kernel_launch(void* const* d_in, const int* in_sizes, int n_in,
                              void* d_out, int out_size) {
    const float* q  = (const float*)d_in[0];
    const float* k  = (const float*)d_in[1];
    const float* v  = (const float*)d_in[2];
    const float* Wk = (const float*)d_in[3];
    // d_in[4] = W_vals (unused by the reference output path)
    float* out = (float*)d_out;

    cudaFuncSetAttribute(k_attn, cudaFuncAttributeMaxDynamicSharedMemorySize, 100352);

    k_bucket_sum   <<<BH*NBUCK, 64>>>(k);
    k_route_sinkhorn<<<BH, 1024>>>(Wk);
    k_kmix         <<<BH*32, 256>>>(k);
    k_attn         <<<BH*NBUCK, 256, 100352>>>(q, v, out);
}

// round 2
// speedup vs baseline: 1.1762x; 1.1762x over previous
#include <cuda_runtime.h>
#include <cstdint>

// Problem constants (fixed by setup_inputs)
#define BH      64      // leading dim of q/k/v (= 4 batch * 16 heads)
#define NH      16      // heads (for W indexing: h = bh & 15)
#define NBUCK   32      // buckets
#define BSZ     128     // bucket size (tokens per bucket)
#define DIM     64      // head dim
#define TOK     4096    // tokens per row
#define ROW     (TOK*DIM)        // 262144 floats per bh row
#define BUCKF   (BSZ*DIM)        // 8192 floats per bucket tile

typedef unsigned long long u64;

// ---- packed f32x2 helpers (Blackwell FFMA2 path, PTX-only) -----------------
__device__ __forceinline__ u64 pack2(float lo, float hi) {
    u64 r; asm("mov.b64 %0,{%1,%2};" : "=l"(r) : "f"(lo), "f"(hi)); return r;
}
__device__ __forceinline__ u64 dup2(float x) {
    u64 r; asm("mov.b64 %0,{%1,%1};" : "=l"(r) : "f"(x)); return r;
}
__device__ __forceinline__ void fma2(u64 &c, u64 a, u64 b) {
    asm("fma.rn.f32x2 %0,%1,%2,%0;" : "+l"(c) : "l"(a), "l"(b));
}
__device__ __forceinline__ float2 unpk(u64 p) {
    float2 f; asm("mov.b64 {%0,%1},%2;" : "=f"(f.x), "=f"(f.y) : "l"(p)); return f;
}

// Scratch (static device arrays; no runtime allocation allowed)
__device__ float g_pl[BH*NBUCK*DIM];        // bucket sums of K
__device__ float g_R [BH*NBUCK*NBUCK];      // sinkhorn routing matrices exp(R)
__device__ float g_kmix[BH*TOK*DIM];        // mixed K

// ---------------------------------------------------------------------------
// K1: pl[bh][i][d] = sum_s k[bh][i*128+s][d]
// ---------------------------------------------------------------------------
__global__ void k_bucket_sum(const float* __restrict__ k) {
    int bid = blockIdx.x;               // 2048 = BH*NBUCK
    int bh = bid >> 5, i = bid & 31, d = threadIdx.x;   // 64 threads
    const float* kb = k + (size_t)bh*ROW + (size_t)i*BUCKF;
    float s = 0.f;
    #pragma unroll 8
    for (int ss = 0; ss < BSZ; ss++) s += kb[ss*DIM + d];
    g_pl[(bh*NBUCK + i)*DIM + d] = s;
}

// ---------------------------------------------------------------------------
// JAX threefry2x32 (partitionable mode, key = jax.random.key(42) -> (0,42)):
// bits[n] = o0 ^ o1 where (o0,o1) = threefry2x32((0,42), (hi=0, lo=n))
// ---------------------------------------------------------------------------
__device__ __forceinline__ uint32_t rotl32(uint32_t x, int r) {
    return (x << r) | (x >> (32 - r));
}
__device__ __forceinline__ uint32_t jax_bits32(uint32_t n) {
    const uint32_t k0 = 0u, k1 = 42u, k2 = 0u ^ 42u ^ 0x1BD11BDAu;
    uint32_t x0 = k0;          // hi counter (0) + ks0
    uint32_t x1 = n + k1;      // lo counter + ks1
#define TF_R(r) { x0 += x1; x1 = rotl32(x1, r); x1 ^= x0; }
    TF_R(13) TF_R(15) TF_R(26) TF_R(6)   x0 += k1; x1 += k2 + 1u;
    TF_R(17) TF_R(29) TF_R(16) TF_R(24)  x0 += k2; x1 += k0 + 2u;
    TF_R(13) TF_R(15) TF_R(26) TF_R(6)   x0 += k0; x1 += k1 + 3u;
    TF_R(17) TF_R(29) TF_R(16) TF_R(24)  x0 += k1; x1 += k2 + 4u;
    TF_R(13) TF_R(15) TF_R(26) TF_R(6)   x0 += k2; x1 += k0 + 5u;
#undef TF_R
    return x0 ^ x1;
}

// ---------------------------------------------------------------------------
// K2: routing + gumbel + 5x sinkhorn + exp.  One block per bh, 1024 threads.
// ---------------------------------------------------------------------------
__global__ __launch_bounds__(1024) void k_route_sinkhorn(const float* __restrict__ Wk) {
    int bh = blockIdx.x;
    int h  = bh & (NH - 1);
    int tid = threadIdx.x;
    int i = tid >> 5, f = tid & 31;

    __shared__ float spl[NBUCK*DIM];   // [i][d]
    __shared__ float sW [DIM*NBUCK];   // [d][f]
    __shared__ float sM [NBUCK*33];    // padded matrix for column reductions

    spl[tid]        = g_pl[bh*(NBUCK*DIM) + tid];
    spl[tid + 1024] = g_pl[bh*(NBUCK*DIM) + tid + 1024];
    sW[tid]         = Wk[h*(DIM*NBUCK) + tid];
    sW[tid + 1024]  = Wk[h*(DIM*NBUCK) + tid + 1024];
    __syncthreads();

    float r = 0.f;
    #pragma unroll
    for (int d = 0; d < DIM; d++) r += spl[i*DIM + d] * sW[d*NBUCK + f];

    // gumbel noise, flat index over R[4,16,32,32]
    uint32_t n = (uint32_t)(bh*1024 + tid);
    uint32_t bits = jax_bits32(n);
    float u = __uint_as_float((bits >> 9) | 0x3f800000u) - 1.0f;
    float g = -logf(-logf(u + 1e-6f) + 1e-6f);
    r = (r + g) / 0.75f;

    for (int it = 0; it < 5; it++) {
        // rows (axis -1): within warp
        float m = r;
        #pragma unroll
        for (int o = 16; o >= 1; o >>= 1) m = fmaxf(m, __shfl_xor_sync(0xffffffffu, m, o));
        float s = expf(r - m);
        #pragma unroll
        for (int o = 16; o >= 1; o >>= 1) s += __shfl_xor_sync(0xffffffffu, s, o);
        r = r - (logf(s) + m);

        // cols (axis -2): via shared
        __syncthreads();
        sM[i*33 + f] = r;
        __syncthreads();
        float cm = -3.4e38f;
        #pragma unroll
        for (int ii = 0; ii < NBUCK; ii++) cm = fmaxf(cm, sM[ii*33 + f]);
        float cs = 0.f;
        #pragma unroll
        for (int ii = 0; ii < NBUCK; ii++) cs += expf(sM[ii*33 + f] - cm);
        r = r - (logf(cs) + cm);
    }
    g_R[bh*1024 + tid] = expf(r);
}

// ---------------------------------------------------------------------------
// K3: Kmix[bh][i][:] = sum_j (R[i][j] + I) * K[bh][j][:]   (f32x2 packed accs)
// ---------------------------------------------------------------------------
__global__ __launch_bounds__(256) void k_kmix(const float* __restrict__ k) {
    int bid = blockIdx.x;               // 2048 = BH * 32 chunks
    int bh = bid >> 5, c = bid & 31;
    int tid = threadIdx.x;

    __shared__ float sA[NBUCK][NBUCK];
    for (int idx = tid; idx < NBUCK*NBUCK; idx += 256) {
        int ii = idx >> 5, jj = idx & 31;
        sA[ii][jj] = g_R[bh*1024 + idx] + ((ii == jj) ? 1.0f : 0.0f);
    }
    __syncthreads();

    const float* kb = k + (size_t)bh*ROW;
    int col = c*256 + tid;              // within [0, 8192)

    u64 acc[NBUCK/2];                   // pair over ii
    #pragma unroll
    for (int p = 0; p < NBUCK/2; p++) acc[p] = 0ull;

    #pragma unroll 4
    for (int j = 0; j < NBUCK; j++) {
        u64 vd = dup2(kb[j*BUCKF + col]);
        #pragma unroll
        for (int p = 0; p < NBUCK/2; p++)
            fma2(acc[p], pack2(sA[2*p][j], sA[2*p+1][j]), vd);
    }
    float* ob = g_kmix + (size_t)bh*ROW;
    #pragma unroll
    for (int p = 0; p < NBUCK/2; p++) {
        float2 f = unpk(acc[p]);
        ob[(2*p  )*BUCKF + col] = f.x;
        ob[(2*p+1)*BUCKF + col] = f.y;
    }
}

// ---------------------------------------------------------------------------
// K4: bucket attention with FFMA2 register-tile GEMMs.
//   GEMM1 128x128x64: acc[8][4] packed along n (B pairs natural from float4,
//                     A duplicated), softmax in regs, GEMM2 128x64x128:
//                     acc[4][4] packed along m (A pairs natural, B dup'd).
// Shared (dynamic, 100352 B):
//   phase1: sQT[64][132] @0, sKT[64][132] @8448
//   phase2: sPT[128][132] @0 (aliases Q/K), sV[128][64] @16896
// ---------------------------------------------------------------------------
#define PAD 132
__global__ __launch_bounds__(256) void k_attn(const float* __restrict__ q,
                                              const float* __restrict__ v,
                                              float* __restrict__ out) {
    extern __shared__ float sm[];
    float* sQT = sm;
    float* sKT = sm + 64*PAD;
    float* sPT = sm;                 // phase 2 alias
    float* sV  = sm + 128*PAD;

    int bid = blockIdx.x;
    size_t base = (size_t)bid * BUCKF;
    const float* qb = q      + base;
    const float* kb = g_kmix + base;
    const float* vb = v      + base;
    float*       ob = out    + base;

    int tid = threadIdx.x;
    for (int idx = tid; idx < BUCKF; idx += 256) {
        int s = idx >> 6, d = idx & 63;
        sQT[d*PAD + s] = qb[idx];
        sKT[d*PAD + s] = kb[idx];
        sV[idx]        = vb[idx];
    }
    __syncthreads();

    int ty = tid >> 4, tx = tid & 15;
    int a0 = 4*ty, a1 = 64 + 4*ty;
    int b0 = 4*tx, b1 = 64 + 4*tx;

    // ---- GEMM1: logits = Q K^T  (acc pairs along n) ----
    u64 cc[8][4];
    #pragma unroll
    for (int m = 0; m < 8; m++)
        #pragma unroll
        for (int p = 0; p < 4; p++) cc[m][p] = 0ull;

    #pragma unroll 4
    for (int d = 0; d < DIM; d++) {
        const float* qd = sQT + d*PAD;
        const float* kd = sKT + d*PAD;
        float4 A0 = *(const float4*)(qd + a0);
        float4 A1 = *(const float4*)(qd + a1);
        float4 B0 = *(const float4*)(kd + b0);
        float4 B1 = *(const float4*)(kd + b1);
        u64 bp[4] = { pack2(B0.x,B0.y), pack2(B0.z,B0.w),
                      pack2(B1.x,B1.y), pack2(B1.z,B1.w) };
        u64 ad[8] = { dup2(A0.x), dup2(A0.y), dup2(A0.z), dup2(A0.w),
                      dup2(A1.x), dup2(A1.y), dup2(A1.z), dup2(A1.w) };
        #pragma unroll
        for (int m = 0; m < 8; m++)
            #pragma unroll
            for (int p = 0; p < 4; p++) fma2(cc[m][p], ad[m], bp[p]);
    }

    // unpack into scalar tile: c[m][n2], n2 0..3 -> cols b0+n2, 4..7 -> b1+n2-4
    float c[8][8];
    #pragma unroll
    for (int m = 0; m < 8; m++)
        #pragma unroll
        for (int p = 0; p < 4; p++) {
            float2 f = unpk(cc[m][p]);
            c[m][2*p] = f.x; c[m][2*p+1] = f.y;
        }

    // ---- softmax over key dim (16 tx lanes per row) ----
    const float scale = 0.125f;   // 1/sqrt(64)
    #pragma unroll
    for (int m = 0; m < 8; m++) {
        float rm = -3.4e38f;
        #pragma unroll
        for (int n2 = 0; n2 < 8; n2++) { c[m][n2] *= scale; rm = fmaxf(rm, c[m][n2]); }
        #pragma unroll
        for (int o = 8; o >= 1; o >>= 1) rm = fmaxf(rm, __shfl_xor_sync(0xffffffffu, rm, o));
        float es = 0.f;
        #pragma unroll
        for (int n2 = 0; n2 < 8; n2++) { c[m][n2] = __expf(c[m][n2] - rm); es += c[m][n2]; }
        #pragma unroll
        for (int o = 8; o >= 1; o >>= 1) es += __shfl_xor_sync(0xffffffffu, es, o);
        float inv = 1.0f / es;
        #pragma unroll
        for (int n2 = 0; n2 < 8; n2++) c[m][n2] *= inv;
    }

    __syncthreads();   // all reads of sQT/sKT complete before aliasing as sPT

    // store P transposed: sPT[j][s] = P[s][j]
    #pragma unroll
    for (int m = 0; m < 8; m++) {
        int row = (m < 4) ? (a0 + m) : (a1 + m - 4);
        #pragma unroll
        for (int n2 = 0; n2 < 8; n2++) {
            int colj = (n2 < 4) ? (b0 + n2) : (b1 + n2 - 4);
            sPT[colj*PAD + row] = c[m][n2];
        }
    }
    __syncthreads();

    // ---- GEMM2: out = P V  (acc pairs along m; A pairs natural) ----
    u64 oo[4][4];
    #pragma unroll
    for (int r = 0; r < 4; r++)
        #pragma unroll
        for (int n2 = 0; n2 < 4; n2++) oo[r][n2] = 0ull;

    #pragma unroll 2
    for (int j = 0; j < BSZ; j++) {
        const float* pj = sPT + j*PAD;
        float4 A0 = *(const float4*)(pj + a0);
        float4 A1 = *(const float4*)(pj + a1);
        float4 B  = *(const float4*)(sV + j*DIM + b0);
        u64 ap[4] = { pack2(A0.x,A0.y), pack2(A0.z,A0.w),
                      pack2(A1.x,A1.y), pack2(A1.z,A1.w) };
        u64 bd[4] = { dup2(B.x), dup2(B.y), dup2(B.z), dup2(B.w) };
        #pragma unroll
        for (int r = 0; r < 4; r++)
            #pragma unroll
            for (int n2 = 0; n2 < 4; n2++) fma2(oo[r][n2], ap[r], bd[n2]);
    }

    // oo[r][n2] = (out[row_pair.lo][b0+n2], out[row_pair.hi][b0+n2])
    #pragma unroll
    for (int r = 0; r < 4; r++) {
        int rowlo = (r < 2) ? (a0 + 2*r) : (a1 + 2*(r-2));
        float2 f0 = unpk(oo[r][0]);
        float2 f1 = unpk(oo[r][1]);
        float2 f2 = unpk(oo[r][2]);
        float2 f3 = unpk(oo[r][3]);
        *(float4*)(ob + rowlo*DIM + b0)     = make_float4(f0.x, f1.x, f2.x, f3.x);
        *(float4*)(ob + (rowlo+1)*DIM + b0) = make_float4(f0.y, f1.y, f2.y, f3.y);
    }
}

// ---------------------------------------------------------------------------
extern "C" void kernel_launch(void* const* d_in, const int* in_sizes, int n_in,
                              void* d_out, int out_size) {
    const float* q  = (const float*)d_in[0];
    const float* k  = (const float*)d_in[1];
    const float* v  = (const float*)d_in[2];
    const float* Wk = (const float*)d_in[3];
    // d_in[4] = W_vals (unused by the reference output path)
    float* out = (float*)d_out;

    cudaFuncSetAttribute(k_attn, cudaFuncAttributeMaxDynamicSharedMemorySize, 100352);

    k_bucket_sum   <<<BH*NBUCK, 64>>>(k);
    k_route_sinkhorn<<<BH, 1024>>>(Wk);
    k_kmix         <<<BH*32, 256>>>(k);
    k_attn         <<<BH*NBUCK, 256, 100352>>>(q, v, out);
}

// round 4
// speedup vs baseline: 1.3251x; 1.1265x over previous
#include <cuda_runtime.h>
#include <cuda_bf16.h>
#include <cstdint>

#define BH      64
#define NH      16
#define NBUCK   32
#define BSZ     128
#define DIM     64
#define TOK     4096
#define ROW     (TOK*DIM)
#define BUCKF   (BSZ*DIM)

typedef unsigned long long u64;
typedef uint32_t u32;

__device__ float g_pl[BH*NBUCK*DIM];
__device__ float g_R [BH*NBUCK*NBUCK];
__device__ float g_kmix[BH*TOK*DIM];

// ---- f32x2 helpers (k_kmix) -------------------------------------------------
__device__ __forceinline__ u64 pack2(float lo, float hi) {
    u64 r; asm("mov.b64 %0,{%1,%2};" : "=l"(r) : "f"(lo), "f"(hi)); return r;
}
__device__ __forceinline__ u64 dup2(float x) {
    u64 r; asm("mov.b64 %0,{%1,%1};" : "=l"(r) : "f"(x)); return r;
}
__device__ __forceinline__ void fma2(u64 &c, u64 a, u64 b) {
    asm("fma.rn.f32x2 %0,%1,%2,%0;" : "+l"(c) : "l"(a), "l"(b));
}
__device__ __forceinline__ float2 unpk(u64 p) {
    float2 f; asm("mov.b64 {%0,%1},%2;" : "=f"(f.x), "=f"(f.y) : "l"(p)); return f;
}

__device__ __forceinline__ u32 smem_u32(const void* p) {
    u32 a; asm("{ .reg .u64 t; cvta.to.shared.u64 t, %1; cvt.u32.u64 %0, t; }"
               : "=r"(a) : "l"(p)); return a;
}

// ---- warp MMA helpers (baseline PTX ISA: ldmatrix + mma.sync, sm_80+) -------
__device__ __forceinline__ void mma16816(float c[4], const u32 a[4], const u32* b) {
    asm volatile("mma.sync.aligned.m16n8k16.row.col.f32.bf16.bf16.f32 "
        "{%0,%1,%2,%3},{%4,%5,%6,%7},{%8,%9},{%0,%1,%2,%3};"
        : "+f"(c[0]), "+f"(c[1]), "+f"(c[2]), "+f"(c[3])
        : "r"(a[0]), "r"(a[1]), "r"(a[2]), "r"(a[3]), "r"(b[0]), "r"(b[1]));
}
// A fragment (m16 x k16), rows at base; quads: (r,k0),(8+r,k0),(r,k16),(8+r,k16)
__device__ __forceinline__ void ldmA(u32 a[4], u32 base, int stride, int lane) {
    int r = lane & 7, q = lane >> 3;
    u32 addr = base + (u32)((r + (q & 1) * 8) * stride + (q >> 1) * 16);
    asm volatile("ldmatrix.sync.aligned.m8n8.x4.shared.b16 {%0,%1,%2,%3}, [%4];"
                 : "=r"(a[0]), "=r"(a[1]), "=r"(a[2]), "=r"(a[3]) : "r"(addr));
}
// B fragments for 2 n-tiles, operand stored [n][k] (k contiguous):
// quads: (n+r,k0),(n+r,k16),(n+8+r,k0),(n+8+r,k16) -> {b0,b1} lo-tile, {b0,b1} hi-tile
__device__ __forceinline__ void ldmB(u32 b[4], u32 base, int stride, int lane) {
    int r = lane & 7, q = lane >> 3;
    u32 addr = base + (u32)((r + (q >> 1) * 8) * stride + (q & 1) * 16);
    asm volatile("ldmatrix.sync.aligned.m8n8.x4.shared.b16 {%0,%1,%2,%3}, [%4];"
                 : "=r"(b[0]), "=r"(b[1]), "=r"(b[2]), "=r"(b[3]) : "r"(addr));
}
// B fragments for 2 n-tiles from [k][n] storage (n contiguous) via .trans:
// quads: (k+r,n0),(k+8+r,n0),(k+r,n0+16B),(k+8+r,n0+16B)
__device__ __forceinline__ void ldmBt(u32 b[4], u32 base, int stride, int lane) {
    int r = lane & 7, q = lane >> 3;
    u32 addr = base + (u32)((r + (q & 1) * 8) * stride + (q >> 1) * 16);
    asm volatile("ldmatrix.sync.aligned.m8n8.x4.trans.shared.b16 {%0,%1,%2,%3}, [%4];"
                 : "=r"(b[0]), "=r"(b[1]), "=r"(b[2]), "=r"(b[3]) : "r"(addr));
}

// ---------------------------------------------------------------------------
// K1: pl[bh][i][d] = sum_s k[...]
// ---------------------------------------------------------------------------
__global__ __launch_bounds__(256) void k_bucket_sum(const float* __restrict__ k) {
    int bid = blockIdx.x;
    int bh = bid >> 5, i = bid & 31;
    int t = threadIdx.x, d = t & 63, g = t >> 6;
    const float* kb = k + (size_t)bh*ROW + (size_t)i*BUCKF;
    float s = 0.f;
    #pragma unroll 8
    for (int ss = g; ss < BSZ; ss += 4) s += kb[ss*DIM + d];
    __shared__ float red[4][64];
    red[g][d] = s;
    __syncthreads();
    if (g == 0)
        g_pl[(bh*NBUCK + i)*DIM + d] = red[0][d] + red[1][d] + red[2][d] + red[3][d];
}

// ---------------------------------------------------------------------------
// JAX threefry2x32 (partitionable), key (0,42)
// ---------------------------------------------------------------------------
__device__ __forceinline__ uint32_t rotl32(uint32_t x, int r) {
    return (x << r) | (x >> (32 - r));
}
__device__ __forceinline__ uint32_t jax_bits32(uint32_t n) {
    const uint32_t k0 = 0u, k1 = 42u, k2 = 0u ^ 42u ^ 0x1BD11BDAu;
    uint32_t x0 = k0;
    uint32_t x1 = n + k1;
#define TF_R(r) { x0 += x1; x1 = rotl32(x1, r); x1 ^= x0; }
    TF_R(13) TF_R(15) TF_R(26) TF_R(6)   x0 += k1; x1 += k2 + 1u;
    TF_R(17) TF_R(29) TF_R(16) TF_R(24)  x0 += k2; x1 += k0 + 2u;
    TF_R(13) TF_R(15) TF_R(26) TF_R(6)   x0 += k0; x1 += k1 + 3u;
    TF_R(17) TF_R(29) TF_R(16) TF_R(24)  x0 += k1; x1 += k2 + 4u;
    TF_R(13) TF_R(15) TF_R(26) TF_R(6)   x0 += k2; x1 += k0 + 5u;
#undef TF_R
    return x0 ^ x1;
}

// ---------------------------------------------------------------------------
// K2: routing + gumbel + sinkhorn + exp
// ---------------------------------------------------------------------------
__global__ __launch_bounds__(1024) void k_route_sinkhorn(const float* __restrict__ Wk) {
    int bh = blockIdx.x;
    int h  = bh & (NH - 1);
    int tid = threadIdx.x;
    int i = tid >> 5, f = tid & 31;

    __shared__ float spl[NBUCK*DIM];
    __shared__ float sW [DIM*NBUCK];
    __shared__ float sM [NBUCK*33];

    spl[tid]        = g_pl[bh*(NBUCK*DIM) + tid];
    spl[tid + 1024] = g_pl[bh*(NBUCK*DIM) + tid + 1024];
    sW[tid]         = Wk[h*(DIM*NBUCK) + tid];
    sW[tid + 1024]  = Wk[h*(DIM*NBUCK) + tid + 1024];
    __syncthreads();

    float r = 0.f;
    #pragma unroll
    for (int d = 0; d < DIM; d++) r += spl[i*DIM + d] * sW[d*NBUCK + f];

    uint32_t n = (uint32_t)(bh*1024 + tid);
    uint32_t bits = jax_bits32(n);
    float u = __uint_as_float((bits >> 9) | 0x3f800000u) - 1.0f;
    float g = -logf(-logf(u + 1e-6f) + 1e-6f);
    r = (r + g) / 0.75f;

    for (int it = 0; it < 5; it++) {
        float m = r;
        #pragma unroll
        for (int o = 16; o >= 1; o >>= 1) m = fmaxf(m, __shfl_xor_sync(0xffffffffu, m, o));
        float s = __expf(r - m);
        #pragma unroll
        for (int o = 16; o >= 1; o >>= 1) s += __shfl_xor_sync(0xffffffffu, s, o);
        r = r - (__logf(s) + m);

        __syncthreads();
        sM[i*33 + f] = r;
        __syncthreads();
        float cm = -3.4e38f;
        #pragma unroll
        for (int ii = 0; ii < NBUCK; ii++) cm = fmaxf(cm, sM[ii*33 + f]);
        float cs = 0.f;
        #pragma unroll
        for (int ii = 0; ii < NBUCK; ii++) cs += __expf(sM[ii*33 + f] - cm);
        r = r - (__logf(cs) + cm);
    }
    g_R[bh*1024 + tid] = __expf(r);
}

// ---------------------------------------------------------------------------
// K3: Kmix = (R+I) @ K
// ---------------------------------------------------------------------------
__global__ __launch_bounds__(256) void k_kmix(const float* __restrict__ k) {
    int bid = blockIdx.x;
    int bh = bid >> 5, c = bid & 31;
    int tid = threadIdx.x;

    __shared__ float sA[NBUCK][NBUCK];
    for (int idx = tid; idx < NBUCK*NBUCK; idx += 256) {
        int ii = idx >> 5, jj = idx & 31;
        sA[ii][jj] = g_R[bh*1024 + idx] + ((ii == jj) ? 1.0f : 0.0f);
    }
    __syncthreads();

    const float* kb = k + (size_t)bh*ROW;
    int col = c*256 + tid;

    u64 acc[NBUCK/2];
    #pragma unroll
    for (int p = 0; p < NBUCK/2; p++) acc[p] = 0ull;

    #pragma unroll 4
    for (int j = 0; j < NBUCK; j++) {
        u64 vd = dup2(kb[j*BUCKF + col]);
        #pragma unroll
        for (int p = 0; p < NBUCK/2; p++)
            fma2(acc[p], pack2(sA[2*p][j], sA[2*p+1][j]), vd);
    }
    float* ob = g_kmix + (size_t)bh*ROW;
    #pragma unroll
    for (int p = 0; p < NBUCK/2; p++) {
        float2 f = unpk(acc[p]);
        ob[(2*p  )*BUCKF + col] = f.x;
        ob[(2*p+1)*BUCKF + col] = f.y;
    }
}

// ---------------------------------------------------------------------------
// K4: bucket attention via ldmatrix + mma.sync bf16 (hi/lo 3-pass split).
// 256 threads = 8 warps.
// GEMM1 (S = QK^T, 128x128x64): warp (wm=w&3, wn=w>>2) -> 32 rows x 64 cols.
// GEMM2 (O = P V, 128x64x128):  warp (wm2=w>>1, wn2=w&1) -> 32 rows x 32 cols.
// SMEM bytes (dynamic, 113152):
//   0      Qh[128][72]bf16 (18432)    } region aliased in phase 2 by
//   18432  Ql                         }  Ph[128][136] @0 (34816)
//   36864  Kh                         }  Pl @34816 (34816)
//   55296  Kl
//   73728  Vh[128][72]                } aliased in epilogue by sO[128][66] f32
//   92160  Vl
//   110592 sPart[2][128]f, 111616 sSum[2][128]f, 112640 sInv[128]f
// ---------------------------------------------------------------------------
#define OFF_QH 0
#define OFF_QL 18432
#define OFF_KH 36864
#define OFF_KL 55296
#define OFF_PH 0
#define OFF_PL 34816
#define OFF_VH 73728
#define OFF_VL 92160
#define OFF_PART 110592
#define OFF_SUM  111616
#define OFF_INV  112640
#define SMEM_TOT 113152
#define SQK 144
#define SP  272
#define SV  144

__global__ __launch_bounds__(256, 2) void k_attn(const float* __restrict__ q,
                                                 const float* __restrict__ v,
                                                 float* __restrict__ out) {
    extern __shared__ char smc[];
    u32 sb = smem_u32(smc);
    int tid = threadIdx.x, w = tid >> 5, lane = tid & 31;

    size_t base = (size_t)blockIdx.x * BUCKF;
    const float* qb = q      + base;
    const float* kb = g_kmix + base;
    const float* vb = v      + base;

    // ---- load + bf16 hi/lo split ----
    for (int i = tid; i < 4096; i += 256) {
        int r = i >> 5, cp = i & 31;
        u32 off = (u32)(r*SQK + cp*4);
        float2 qv = *(const float2*)(qb + r*64 + cp*2);
        qv.x *= 0.125f; qv.y *= 0.125f;
        __nv_bfloat162 qh = __floats2bfloat162_rn(qv.x, qv.y);
        __nv_bfloat162 ql = __floats2bfloat162_rn(qv.x - __bfloat162float(qh.x),
                                                  qv.y - __bfloat162float(qh.y));
        *(u32*)(smc + OFF_QH + off) = *(u32*)&qh;
        *(u32*)(smc + OFF_QL + off) = *(u32*)&ql;
        float2 kv = *(const float2*)(kb + r*64 + cp*2);
        __nv_bfloat162 kh = __floats2bfloat162_rn(kv.x, kv.y);
        __nv_bfloat162 kl = __floats2bfloat162_rn(kv.x - __bfloat162float(kh.x),
                                                  kv.y - __bfloat162float(kh.y));
        *(u32*)(smc + OFF_KH + off) = *(u32*)&kh;
        *(u32*)(smc + OFF_KL + off) = *(u32*)&kl;
        float2 vv = *(const float2*)(vb + r*64 + cp*2);
        __nv_bfloat162 vh = __floats2bfloat162_rn(vv.x, vv.y);
        __nv_bfloat162 vl = __floats2bfloat162_rn(vv.x - __bfloat162float(vh.x),
                                                  vv.y - __bfloat162float(vh.y));
        *(u32*)(smc + OFF_VH + off) = *(u32*)&vh;
        *(u32*)(smc + OFF_VL + off) = *(u32*)&vl;
    }
    __syncthreads();

    // ---- GEMM1: S = Q K^T  (3 passes: hh, hl, lh) ----
    int wm = w & 3, wn = w >> 2;
    float acc[2][8][4];
    #pragma unroll
    for (int mt = 0; mt < 2; mt++)
        #pragma unroll
        for (int nt = 0; nt < 8; nt++)
            #pragma unroll
            for (int e = 0; e < 4; e++) acc[mt][nt][e] = 0.f;

    #pragma unroll
    for (int pass = 0; pass < 3; pass++) {
        u32 Ab = sb + (pass == 2 ? OFF_QL : OFF_QH) + wm*32*SQK;
        u32 Bb = sb + (pass == 1 ? OFF_KL : OFF_KH) + wn*64*SQK;
        #pragma unroll
        for (int ks = 0; ks < 4; ks++) {
            u32 a[2][4], b[4][4];
            ldmA(a[0], Ab + ks*32,           SQK, lane);
            ldmA(a[1], Ab + 16*SQK + ks*32,  SQK, lane);
            #pragma unroll
            for (int np = 0; np < 4; np++)
                ldmB(b[np], Bb + np*16*SQK + ks*32, SQK, lane);
            #pragma unroll
            for (int mt = 0; mt < 2; mt++)
                #pragma unroll
                for (int nt = 0; nt < 8; nt++)
                    mma16816(acc[mt][nt], a[mt], &b[nt >> 1][(nt & 1)*2]);
        }
    }

    // ---- softmax over key dim ----
    float* sPart = (float*)(smc + OFF_PART);
    float* sSum  = (float*)(smc + OFF_SUM);
    float* sInv  = (float*)(smc + OFF_INV);
    int g = lane >> 2, qd = lane & 3;

    float mx[2][2];
    #pragma unroll
    for (int mt = 0; mt < 2; mt++) {
        float m0 = -3.4e38f, m1 = -3.4e38f;
        #pragma unroll
        for (int nt = 0; nt < 8; nt++) {
            m0 = fmaxf(m0, fmaxf(acc[mt][nt][0], acc[mt][nt][1]));
            m1 = fmaxf(m1, fmaxf(acc[mt][nt][2], acc[mt][nt][3]));
        }
        m0 = fmaxf(m0, __shfl_xor_sync(0xffffffffu, m0, 1));
        m0 = fmaxf(m0, __shfl_xor_sync(0xffffffffu, m0, 2));
        m1 = fmaxf(m1, __shfl_xor_sync(0xffffffffu, m1, 1));
        m1 = fmaxf(m1, __shfl_xor_sync(0xffffffffu, m1, 2));
        mx[mt][0] = m0; mx[mt][1] = m1;
        if (qd == 0) {
            int row = wm*32 + mt*16 + g;
            sPart[wn*128 + row]     = m0;
            sPart[wn*128 + row + 8] = m1;
        }
    }
    __syncthreads();

    float sums[2][2];
    #pragma unroll
    for (int mt = 0; mt < 2; mt++) {
        int row = wm*32 + mt*16 + g;
        float gm0 = fmaxf(sPart[row],     sPart[128 + row]);
        float gm1 = fmaxf(sPart[row + 8], sPart[128 + row + 8]);
        float e0 = 0.f, e1 = 0.f;
        #pragma unroll
        for (int nt = 0; nt < 8; nt++) {
            acc[mt][nt][0] = __expf(acc[mt][nt][0] - gm0);
            acc[mt][nt][1] = __expf(acc[mt][nt][1] - gm0);
            acc[mt][nt][2] = __expf(acc[mt][nt][2] - gm1);
            acc[mt][nt][3] = __expf(acc[mt][nt][3] - gm1);
            e0 += acc[mt][nt][0] + acc[mt][nt][1];
            e1 += acc[mt][nt][2] + acc[mt][nt][3];
        }
        e0 += __shfl_xor_sync(0xffffffffu, e0, 1);
        e0 += __shfl_xor_sync(0xffffffffu, e0, 2);
        e1 += __shfl_xor_sync(0xffffffffu, e1, 1);
        e1 += __shfl_xor_sync(0xffffffffu, e1, 2);
        sums[mt][0] = e0; sums[mt][1] = e1;
        if (qd == 0) {
            sSum[wn*128 + row]     = e0;
            sSum[wn*128 + row + 8] = e1;
        }
    }

    // ---- convert unnormalized P to bf16 hi/lo, store into aliased Q/K smem ----
    // (safe: every warp finished its GEMM1 smem reads, and the sPart
    //  __syncthreads above globally ordered reads before these writes)
    #pragma unroll
    for (int mt = 0; mt < 2; mt++) {
        int row0 = wm*32 + mt*16 + g;
        #pragma unroll
        for (int nt = 0; nt < 8; nt++) {
            u32 cb = (u32)(wn*128 + nt*16 + qd*4);
            __nv_bfloat162 h0 = __floats2bfloat162_rn(acc[mt][nt][0], acc[mt][nt][1]);
            __nv_bfloat162 l0 = __floats2bfloat162_rn(acc[mt][nt][0] - __bfloat162float(h0.x),
                                                      acc[mt][nt][1] - __bfloat162float(h0.y));
            *(u32*)(smc + OFF_PH + row0*SP + cb) = *(u32*)&h0;
            *(u32*)(smc + OFF_PL + row0*SP + cb) = *(u32*)&l0;
            __nv_bfloat162 h1 = __floats2bfloat162_rn(acc[mt][nt][2], acc[mt][nt][3]);
            __nv_bfloat162 l1 = __floats2bfloat162_rn(acc[mt][nt][2] - __bfloat162float(h1.x),
                                                      acc[mt][nt][3] - __bfloat162float(h1.y));
            *(u32*)(smc + OFF_PH + (row0+8)*SP + cb) = *(u32*)&h1;
            *(u32*)(smc + OFF_PL + (row0+8)*SP + cb) = *(u32*)&l1;
        }
    }
    __syncthreads();

    if (wn == 0 && qd == 0) {
        #pragma unroll
        for (int mt = 0; mt < 2; mt++) {
            int row = wm*32 + mt*16 + g;
            sInv[row]     = 1.0f / (sSum[row]     + sSum[128 + row]);
            sInv[row + 8] = 1.0f / (sSum[row + 8] + sSum[128 + row + 8]);
        }
    }

    // ---- GEMM2: O = P V  (3 passes: hh, hl, lh) ----
    int wn2 = w & 1, wm2 = w >> 1;
    float o[2][4][4];
    #pragma unroll
    for (int mt = 0; mt < 2; mt++)
        #pragma unroll
        for (int nt = 0; nt < 4; nt++)
            #pragma unroll
            for (int e = 0; e < 4; e++) o[mt][nt][e] = 0.f;

    #pragma unroll
    for (int pass = 0; pass < 3; pass++) {
        u32 Ab = sb + (pass == 2 ? OFF_PL : OFF_PH) + wm2*32*SP;
        u32 Bb = sb + (pass == 1 ? OFF_VL : OFF_VH) + wn2*64;
        #pragma unroll
        for (int ks = 0; ks < 8; ks++) {
            u32 a[2][4], b[2][4];
            ldmA(a[0], Ab + ks*32,          SP, lane);
            ldmA(a[1], Ab + 16*SP + ks*32,  SP, lane);
            ldmBt(b[0], Bb + ks*16*SV,      SV, lane);
            ldmBt(b[1], Bb + ks*16*SV + 32, SV, lane);
            #pragma unroll
            for (int mt = 0; mt < 2; mt++)
                #pragma unroll
                for (int nt = 0; nt < 4; nt++)
                    mma16816(o[mt][nt], a[mt], &b[nt >> 1][(nt & 1)*2]);
        }
    }
    __syncthreads();     // all warps done reading V smem before aliasing as sO

    // ---- epilogue: normalize, stage in smem (stride 66), coalesced store ----
    float* sO = (float*)(smc + OFF_VH);
    #pragma unroll
    for (int mt = 0; mt < 2; mt++) {
        int row0 = wm2*32 + mt*16 + g;
        float inv0 = sInv[row0], inv1 = sInv[row0 + 8];
        #pragma unroll
        for (int nt = 0; nt < 4; nt++) {
            int col = wn2*32 + nt*8 + qd*2;
            sO[row0*66 + col]       = o[mt][nt][0] * inv0;
            sO[row0*66 + col + 1]   = o[mt][nt][1] * inv0;
            sO[(row0+8)*66 + col]   = o[mt][nt][2] * inv1;
            sO[(row0+8)*66 + col+1] = o[mt][nt][3] * inv1;
        }
    }
    __syncthreads();

    float* ob = out + base;
    for (int i = tid; i < 4096; i += 256) {
        int r = i >> 5, p = i & 31;
        float2 val = *(const float2*)(sO + r*66 + p*2);
        *(float2*)(ob + r*64 + p*2) = val;
    }
}

// ---------------------------------------------------------------------------
extern "C" void kernel_launch(void* const* d_in, const int* in_sizes, int n_in,
                              void* d_out, int out_size) {
    const float* q  = (const float*)d_in[0];
    const float* k  = (const float*)d_in[1];
    const float* v  = (const float*)d_in[2];
    const float* Wk = (const float*)d_in[3];
    float* out = (float*)d_out;

    cudaFuncSetAttribute(k_attn, cudaFuncAttributeMaxDynamicSharedMemorySize, SMEM_TOT);

    k_bucket_sum    <<<BH*NBUCK, 256>>>(k);
    k_route_sinkhorn<<<BH, 1024>>>(Wk);
    k_kmix          <<<BH*32, 256>>>(k);
    k_attn          <<<BH*NBUCK, 256, SMEM_TOT>>>(q, v, out);
}

// round 5
// speedup vs baseline: 1.6826x; 1.2698x over previous
#include <cuda_runtime.h>
#include <cuda_bf16.h>
#include <cstdint>

#define BH      64
#define NH      16
#define NBUCK   32
#define BSZ     128
#define DIM     64
#define TOK     4096
#define ROW     (TOK*DIM)
#define BUCKF   (BSZ*DIM)

typedef unsigned long long u64;
typedef uint32_t u32;

__device__ float g_pl[BH*NBUCK*DIM];
__device__ float g_R [BH*NBUCK*NBUCK];
__device__ float g_kmix[BH*TOK*DIM];

// ---- f32x2 helpers ----------------------------------------------------------
__device__ __forceinline__ u64 pack2(float lo, float hi) {
    u64 r; asm("mov.b64 %0,{%1,%2};" : "=l"(r) : "f"(lo), "f"(hi)); return r;
}
__device__ __forceinline__ u64 dup2(float x) {
    u64 r; asm("mov.b64 %0,{%1,%1};" : "=l"(r) : "f"(x)); return r;
}
__device__ __forceinline__ void fma2(u64 &c, u64 a, u64 b) {
    asm("fma.rn.f32x2 %0,%1,%2,%0;" : "+l"(c) : "l"(a), "l"(b));
}
__device__ __forceinline__ float2 unpk(u64 p) {
    float2 f; asm("mov.b64 {%0,%1},%2;" : "=f"(f.x), "=f"(f.y) : "l"(p)); return f;
}

__device__ __forceinline__ u32 smem_u32(const void* p) {
    u32 a; asm("{ .reg .u64 t; cvta.to.shared.u64 t, %1; cvt.u32.u64 %0, t; }"
               : "=r"(a) : "l"(p)); return a;
}

// ---- warp MMA helpers (baseline PTX ISA) ------------------------------------
__device__ __forceinline__ void mma16816(float c[4], const u32 a[4], const u32* b) {
    asm volatile("mma.sync.aligned.m16n8k16.row.col.f32.bf16.bf16.f32 "
        "{%0,%1,%2,%3},{%4,%5,%6,%7},{%8,%9},{%0,%1,%2,%3};"
        : "+f"(c[0]), "+f"(c[1]), "+f"(c[2]), "+f"(c[3])
        : "r"(a[0]), "r"(a[1]), "r"(a[2]), "r"(a[3]), "r"(b[0]), "r"(b[1]));
}
__device__ __forceinline__ void ldmA(u32 a[4], u32 base, int stride, int lane) {
    int r = lane & 7, q = lane >> 3;
    u32 addr = base + (u32)((r + (q & 1) * 8) * stride + (q >> 1) * 16);
    asm volatile("ldmatrix.sync.aligned.m8n8.x4.shared.b16 {%0,%1,%2,%3}, [%4];"
                 : "=r"(a[0]), "=r"(a[1]), "=r"(a[2]), "=r"(a[3]) : "r"(addr));
}
__device__ __forceinline__ void ldmB(u32 b[4], u32 base, int stride, int lane) {
    int r = lane & 7, q = lane >> 3;
    u32 addr = base + (u32)((r + (q >> 1) * 8) * stride + (q & 1) * 16);
    asm volatile("ldmatrix.sync.aligned.m8n8.x4.shared.b16 {%0,%1,%2,%3}, [%4];"
                 : "=r"(b[0]), "=r"(b[1]), "=r"(b[2]), "=r"(b[3]) : "r"(addr));
}
__device__ __forceinline__ void ldmBt(u32 b[4], u32 base, int stride, int lane) {
    int r = lane & 7, q = lane >> 3;
    u32 addr = base + (u32)((r + (q & 1) * 8) * stride + (q >> 1) * 16);
    asm volatile("ldmatrix.sync.aligned.m8n8.x4.trans.shared.b16 {%0,%1,%2,%3}, [%4];"
                 : "=r"(b[0]), "=r"(b[1]), "=r"(b[2]), "=r"(b[3]) : "r"(addr));
}

// ---------------------------------------------------------------------------
// K1: pl[bh][i][d] = sum_s k[...]  (float2 loads)
// ---------------------------------------------------------------------------
__global__ __launch_bounds__(256) void k_bucket_sum(const float* __restrict__ k) {
    int bid = blockIdx.x;               // 2048
    int bh = bid >> 5, i = bid & 31;
    int t = threadIdx.x, c = t & 31, g = t >> 5;    // c: float2 col, g: 0..7
    const float2* kb2 = (const float2*)(k + (size_t)bh*ROW + (size_t)i*BUCKF);
    float sx = 0.f, sy = 0.f;
    #pragma unroll 4
    for (int ss = g; ss < BSZ; ss += 8) {
        float2 vv = kb2[ss*32 + c];
        sx += vv.x; sy += vv.y;
    }
    __shared__ float2 red[8][32];
    red[g][c] = make_float2(sx, sy);
    __syncthreads();
    if (g == 0) {
        #pragma unroll
        for (int gg = 1; gg < 8; gg++) { sx += red[gg][c].x; sy += red[gg][c].y; }
        float* dst = g_pl + (bh*NBUCK + i)*DIM;
        dst[2*c]   = sx;
        dst[2*c+1] = sy;
    }
}

// ---------------------------------------------------------------------------
// JAX threefry2x32 (partitionable), key (0,42)
// ---------------------------------------------------------------------------
__device__ __forceinline__ uint32_t rotl32(uint32_t x, int r) {
    return (x << r) | (x >> (32 - r));
}
__device__ __forceinline__ uint32_t jax_bits32(uint32_t n) {
    const uint32_t k0 = 0u, k1 = 42u, k2 = 0u ^ 42u ^ 0x1BD11BDAu;
    uint32_t x0 = k0;
    uint32_t x1 = n + k1;
#define TF_R(r) { x0 += x1; x1 = rotl32(x1, r); x1 ^= x0; }
    TF_R(13) TF_R(15) TF_R(26) TF_R(6)   x0 += k1; x1 += k2 + 1u;
    TF_R(17) TF_R(29) TF_R(16) TF_R(24)  x0 += k2; x1 += k0 + 2u;
    TF_R(13) TF_R(15) TF_R(26) TF_R(6)   x0 += k0; x1 += k1 + 3u;
    TF_R(17) TF_R(29) TF_R(16) TF_R(24)  x0 += k1; x1 += k2 + 4u;
    TF_R(13) TF_R(15) TF_R(26) TF_R(6)   x0 += k2; x1 += k0 + 5u;
#undef TF_R
    return x0 ^ x1;
}

// ---------------------------------------------------------------------------
// K2: routing + gumbel + sinkhorn + exp
// ---------------------------------------------------------------------------
__global__ __launch_bounds__(1024) void k_route_sinkhorn(const float* __restrict__ Wk) {
    int bh = blockIdx.x;
    int h  = bh & (NH - 1);
    int tid = threadIdx.x;
    int i = tid >> 5, f = tid & 31;

    __shared__ float spl[NBUCK*DIM];
    __shared__ float sW [DIM*NBUCK];
    __shared__ float sM [NBUCK*33];

    spl[tid]        = g_pl[bh*(NBUCK*DIM) + tid];
    spl[tid + 1024] = g_pl[bh*(NBUCK*DIM) + tid + 1024];
    sW[tid]         = Wk[h*(DIM*NBUCK) + tid];
    sW[tid + 1024]  = Wk[h*(DIM*NBUCK) + tid + 1024];
    __syncthreads();

    float r = 0.f;
    #pragma unroll
    for (int d = 0; d < DIM; d++) r += spl[i*DIM + d] * sW[d*NBUCK + f];

    uint32_t n = (uint32_t)(bh*1024 + tid);
    uint32_t bits = jax_bits32(n);
    float u = __uint_as_float((bits >> 9) | 0x3f800000u) - 1.0f;
    float g = -logf(-logf(u + 1e-6f) + 1e-6f);
    r = (r + g) / 0.75f;

    for (int it = 0; it < 5; it++) {
        float m = r;
        #pragma unroll
        for (int o = 16; o >= 1; o >>= 1) m = fmaxf(m, __shfl_xor_sync(0xffffffffu, m, o));
        float s = __expf(r - m);
        #pragma unroll
        for (int o = 16; o >= 1; o >>= 1) s += __shfl_xor_sync(0xffffffffu, s, o);
        r = r - (__logf(s) + m);

        __syncthreads();
        sM[i*33 + f] = r;
        __syncthreads();
        float cm = -3.4e38f;
        #pragma unroll
        for (int ii = 0; ii < NBUCK; ii++) cm = fmaxf(cm, sM[ii*33 + f]);
        float cs = 0.f;
        #pragma unroll
        for (int ii = 0; ii < NBUCK; ii++) cs += __expf(sM[ii*33 + f] - cm);
        r = r - (__logf(cs) + cm);
    }
    g_R[bh*1024 + tid] = __expf(r);
}

// ---------------------------------------------------------------------------
// K3: Kmix = (R+I) @ K  -- float2 cols, f32x2 packed over row pairs
// grid = BH*16, 256 threads; thread owns one float2 column (2 floats).
// ---------------------------------------------------------------------------
__global__ __launch_bounds__(256) void k_kmix(const float* __restrict__ k) {
    int bid = blockIdx.x;               // 1024
    int bh = bid >> 4, c = bid & 15;
    int tid = threadIdx.x;

    __shared__ float sA[NBUCK][NBUCK];
    for (int idx = tid; idx < NBUCK*NBUCK; idx += 256) {
        int ii = idx >> 5, jj = idx & 31;
        sA[ii][jj] = g_R[bh*1024 + idx] + ((ii == jj) ? 1.0f : 0.0f);
    }
    __syncthreads();

    const float2* kb2 = (const float2*)(k + (size_t)bh*ROW);
    int col2 = c*256 + tid;             // float2 index in [0,4096)

    u64 ax[NBUCK/2], ay[NBUCK/2];
    #pragma unroll
    for (int p = 0; p < NBUCK/2; p++) { ax[p] = 0ull; ay[p] = 0ull; }

    #pragma unroll 2
    for (int j = 0; j < NBUCK; j++) {
        float2 kv = kb2[j*4096 + col2];
        u64 vx = dup2(kv.x), vy = dup2(kv.y);
        #pragma unroll
        for (int p = 0; p < NBUCK/2; p++) {
            u64 ap = pack2(sA[2*p][j], sA[2*p+1][j]);
            fma2(ax[p], ap, vx);
            fma2(ay[p], ap, vy);
        }
    }
    float2* ob2 = (float2*)(g_kmix + (size_t)bh*ROW);
    #pragma unroll
    for (int p = 0; p < NBUCK/2; p++) {
        float2 fx = unpk(ax[p]);   // (row 2p, row 2p+1) at col x
        float2 fy = unpk(ay[p]);
        ob2[(2*p  )*4096 + col2] = make_float2(fx.x, fy.x);
        ob2[(2*p+1)*4096 + col2] = make_float2(fx.y, fy.y);
    }
}

// ---------------------------------------------------------------------------
// K4: bucket attention via ldmatrix + mma.sync bf16 (hi/lo 3-pass split)
// with merged-pass A-fragment reuse + float4 load phase.
// ---------------------------------------------------------------------------
#define OFF_QH 0
#define OFF_QL 18432
#define OFF_KH 36864
#define OFF_KL 55296
#define OFF_PH 0
#define OFF_PL 34816
#define OFF_VH 73728
#define OFF_VL 92160
#define OFF_PART 110592
#define OFF_SUM  111616
#define OFF_INV  112640
#define SMEM_TOT 113152
#define SQK 144
#define SP  272
#define SV  144

__global__ __launch_bounds__(256, 2) void k_attn(const float* __restrict__ q,
                                                 const float* __restrict__ v,
                                                 float* __restrict__ out) {
    extern __shared__ char smc[];
    u32 sb = smem_u32(smc);
    int tid = threadIdx.x, w = tid >> 5, lane = tid & 31;

    size_t base = (size_t)blockIdx.x * BUCKF;
    const float* qb = q      + base;
    const float* kb = g_kmix + base;
    const float* vb = v      + base;

    // ---- load + bf16 hi/lo split (float4 gmem, u64 smem stores) ----
    for (int i = tid; i < 2048; i += 256) {          // 8 iters
        int r = i >> 4, c4 = i & 15;
        u32 off = (u32)(r*SQK + c4*8);

        float4 qv = *(const float4*)(qb + r*64 + c4*4);
        qv.x *= 0.125f; qv.y *= 0.125f; qv.z *= 0.125f; qv.w *= 0.125f;
        __nv_bfloat162 qh0 = __floats2bfloat162_rn(qv.x, qv.y);
        __nv_bfloat162 qh1 = __floats2bfloat162_rn(qv.z, qv.w);
        __nv_bfloat162 ql0 = __floats2bfloat162_rn(qv.x - __bfloat162float(qh0.x),
                                                   qv.y - __bfloat162float(qh0.y));
        __nv_bfloat162 ql1 = __floats2bfloat162_rn(qv.z - __bfloat162float(qh1.x),
                                                   qv.w - __bfloat162float(qh1.y));
        *(u64*)(smc + OFF_QH + off) = ((u64)*(u32*)&qh1 << 32) | *(u32*)&qh0;
        *(u64*)(smc + OFF_QL + off) = ((u64)*(u32*)&ql1 << 32) | *(u32*)&ql0;

        float4 kv = *(const float4*)(kb + r*64 + c4*4);
        __nv_bfloat162 kh0 = __floats2bfloat162_rn(kv.x, kv.y);
        __nv_bfloat162 kh1 = __floats2bfloat162_rn(kv.z, kv.w);
        __nv_bfloat162 kl0 = __floats2bfloat162_rn(kv.x - __bfloat162float(kh0.x),
                                                   kv.y - __bfloat162float(kh0.y));
        __nv_bfloat162 kl1 = __floats2bfloat162_rn(kv.z - __bfloat162float(kh1.x),
                                                   kv.w - __bfloat162float(kh1.y));
        *(u64*)(smc + OFF_KH + off) = ((u64)*(u32*)&kh1 << 32) | *(u32*)&kh0;
        *(u64*)(smc + OFF_KL + off) = ((u64)*(u32*)&kl1 << 32) | *(u32*)&kl0;

        float4 vv = *(const float4*)(vb + r*64 + c4*4);
        __nv_bfloat162 vh0 = __floats2bfloat162_rn(vv.x, vv.y);
        __nv_bfloat162 vh1 = __floats2bfloat162_rn(vv.z, vv.w);
        __nv_bfloat162 vl0 = __floats2bfloat162_rn(vv.x - __bfloat162float(vh0.x),
                                                   vv.y - __bfloat162float(vh0.y));
        __nv_bfloat162 vl1 = __floats2bfloat162_rn(vv.z - __bfloat162float(vh1.x),
                                                   vv.w - __bfloat162float(vh1.y));
        *(u64*)(smc + OFF_VH + off) = ((u64)*(u32*)&vh1 << 32) | *(u32*)&vh0;
        *(u64*)(smc + OFF_VL + off) = ((u64)*(u32*)&vl1 << 32) | *(u32*)&vl0;
    }
    __syncthreads();

    // ---- GEMM1: S = Q K^T (merged: A=Qh -> B=Kh,Kl; then A=Ql -> B=Kh) ----
    int wm = w & 3, wn = w >> 2;
    float acc[2][8][4];
    #pragma unroll
    for (int mt = 0; mt < 2; mt++)
        #pragma unroll
        for (int nt = 0; nt < 8; nt++)
            #pragma unroll
            for (int e = 0; e < 4; e++) acc[mt][nt][e] = 0.f;

    {
        u32 AbH = sb + OFF_QH + wm*32*SQK;
        u32 AbL = sb + OFF_QL + wm*32*SQK;
        u32 BbH = sb + OFF_KH + wn*64*SQK;
        u32 BbL = sb + OFF_KL + wn*64*SQK;
        #pragma unroll
        for (int ks = 0; ks < 4; ks++) {
            u32 a[2][4], b[4][4];
            ldmA(a[0], AbH + ks*32,          SQK, lane);
            ldmA(a[1], AbH + 16*SQK + ks*32, SQK, lane);
            #pragma unroll
            for (int np = 0; np < 4; np++)
                ldmB(b[np], BbH + np*16*SQK + ks*32, SQK, lane);
            #pragma unroll
            for (int mt = 0; mt < 2; mt++)
                #pragma unroll
                for (int nt = 0; nt < 8; nt++)
                    mma16816(acc[mt][nt], a[mt], &b[nt >> 1][(nt & 1)*2]);
            #pragma unroll
            for (int np = 0; np < 4; np++)
                ldmB(b[np], BbL + np*16*SQK + ks*32, SQK, lane);
            #pragma unroll
            for (int mt = 0; mt < 2; mt++)
                #pragma unroll
                for (int nt = 0; nt < 8; nt++)
                    mma16816(acc[mt][nt], a[mt], &b[nt >> 1][(nt & 1)*2]);
        }
        #pragma unroll
        for (int ks = 0; ks < 4; ks++) {
            u32 a[2][4], b[4][4];
            ldmA(a[0], AbL + ks*32,          SQK, lane);
            ldmA(a[1], AbL + 16*SQK + ks*32, SQK, lane);
            #pragma unroll
            for (int np = 0; np < 4; np++)
                ldmB(b[np], BbH + np*16*SQK + ks*32, SQK, lane);
            #pragma unroll
            for (int mt = 0; mt < 2; mt++)
                #pragma unroll
                for (int nt = 0; nt < 8; nt++)
                    mma16816(acc[mt][nt], a[mt], &b[nt >> 1][(nt & 1)*2]);
        }
    }

    // ---- softmax over key dim ----
    float* sPart = (float*)(smc + OFF_PART);
    float* sSum  = (float*)(smc + OFF_SUM);
    float* sInv  = (float*)(smc + OFF_INV);
    int g = lane >> 2, qd = lane & 3;

    #pragma unroll
    for (int mt = 0; mt < 2; mt++) {
        float m0 = -3.4e38f, m1 = -3.4e38f;
        #pragma unroll
        for (int nt = 0; nt < 8; nt++) {
            m0 = fmaxf(m0, fmaxf(acc[mt][nt][0], acc[mt][nt][1]));
            m1 = fmaxf(m1, fmaxf(acc[mt][nt][2], acc[mt][nt][3]));
        }
        m0 = fmaxf(m0, __shfl_xor_sync(0xffffffffu, m0, 1));
        m0 = fmaxf(m0, __shfl_xor_sync(0xffffffffu, m0, 2));
        m1 = fmaxf(m1, __shfl_xor_sync(0xffffffffu, m1, 1));
        m1 = fmaxf(m1, __shfl_xor_sync(0xffffffffu, m1, 2));
        if (qd == 0) {
            int row = wm*32 + mt*16 + g;
            sPart[wn*128 + row]     = m0;
            sPart[wn*128 + row + 8] = m1;
        }
    }
    __syncthreads();

    #pragma unroll
    for (int mt = 0; mt < 2; mt++) {
        int row = wm*32 + mt*16 + g;
        float gm0 = fmaxf(sPart[row],     sPart[128 + row]);
        float gm1 = fmaxf(sPart[row + 8], sPart[128 + row + 8]);
        float e0 = 0.f, e1 = 0.f;
        #pragma unroll
        for (int nt = 0; nt < 8; nt++) {
            acc[mt][nt][0] = __expf(acc[mt][nt][0] - gm0);
            acc[mt][nt][1] = __expf(acc[mt][nt][1] - gm0);
            acc[mt][nt][2] = __expf(acc[mt][nt][2] - gm1);
            acc[mt][nt][3] = __expf(acc[mt][nt][3] - gm1);
            e0 += acc[mt][nt][0] + acc[mt][nt][1];
            e1 += acc[mt][nt][2] + acc[mt][nt][3];
        }
        e0 += __shfl_xor_sync(0xffffffffu, e0, 1);
        e0 += __shfl_xor_sync(0xffffffffu, e0, 2);
        e1 += __shfl_xor_sync(0xffffffffu, e1, 1);
        e1 += __shfl_xor_sync(0xffffffffu, e1, 2);
        if (qd == 0) {
            sSum[wn*128 + row]     = e0;
            sSum[wn*128 + row + 8] = e1;
        }
    }

    // ---- convert unnormalized P to bf16 hi/lo into aliased Q/K smem ----
    #pragma unroll
    for (int mt = 0; mt < 2; mt++) {
        int row0 = wm*32 + mt*16 + g;
        #pragma unroll
        for (int nt = 0; nt < 8; nt++) {
            u32 cb = (u32)(wn*128 + nt*16 + qd*4);
            __nv_bfloat162 h0 = __floats2bfloat162_rn(acc[mt][nt][0], acc[mt][nt][1]);
            __nv_bfloat162 l0 = __floats2bfloat162_rn(acc[mt][nt][0] - __bfloat162float(h0.x),
                                                      acc[mt][nt][1] - __bfloat162float(h0.y));
            *(u32*)(smc + OFF_PH + row0*SP + cb) = *(u32*)&h0;
            *(u32*)(smc + OFF_PL + row0*SP + cb) = *(u32*)&l0;
            __nv_bfloat162 h1 = __floats2bfloat162_rn(acc[mt][nt][2], acc[mt][nt][3]);
            __nv_bfloat162 l1 = __floats2bfloat162_rn(acc[mt][nt][2] - __bfloat162float(h1.x),
                                                      acc[mt][nt][3] - __bfloat162float(h1.y));
            *(u32*)(smc + OFF_PH + (row0+8)*SP + cb) = *(u32*)&h1;
            *(u32*)(smc + OFF_PL + (row0+8)*SP + cb) = *(u32*)&l1;
        }
    }
    __syncthreads();

    if (wn == 0 && qd == 0) {
        #pragma unroll
        for (int mt = 0; mt < 2; mt++) {
            int row = wm*32 + mt*16 + g;
            sInv[row]     = 1.0f / (sSum[row]     + sSum[128 + row]);
            sInv[row + 8] = 1.0f / (sSum[row + 8] + sSum[128 + row + 8]);
        }
    }

    // ---- GEMM2: O = P V (merged: A=Ph -> B=Vh,Vl; then A=Pl -> B=Vh) ----
    int wn2 = w & 1, wm2 = w >> 1;
    float o[2][4][4];
    #pragma unroll
    for (int mt = 0; mt < 2; mt++)
        #pragma unroll
        for (int nt = 0; nt < 4; nt++)
            #pragma unroll
            for (int e = 0; e < 4; e++) o[mt][nt][e] = 0.f;

    {
        u32 AbH = sb + OFF_PH + wm2*32*SP;
        u32 AbL = sb + OFF_PL + wm2*32*SP;
        u32 BbH = sb + OFF_VH + wn2*64;
        u32 BbL = sb + OFF_VL + wn2*64;
        #pragma unroll
        for (int ks = 0; ks < 8; ks++) {
            u32 a[2][4], b[2][4];
            ldmA(a[0], AbH + ks*32,         SP, lane);
            ldmA(a[1], AbH + 16*SP + ks*32, SP, lane);
            ldmBt(b[0], BbH + ks*16*SV,      SV, lane);
            ldmBt(b[1], BbH + ks*16*SV + 32, SV, lane);
            #pragma unroll
            for (int mt = 0; mt < 2; mt++)
                #pragma unroll
                for (int nt = 0; nt < 4; nt++)
                    mma16816(o[mt][nt], a[mt], &b[nt >> 1][(nt & 1)*2]);
            ldmBt(b[0], BbL + ks*16*SV,      SV, lane);
            ldmBt(b[1], BbL + ks*16*SV + 32, SV, lane);
            #pragma unroll
            for (int mt = 0; mt < 2; mt++)
                #pragma unroll
                for (int nt = 0; nt < 4; nt++)
                    mma16816(o[mt][nt], a[mt], &b[nt >> 1][(nt & 1)*2]);
        }
        #pragma unroll
        for (int ks = 0; ks < 8; ks++) {
            u32 a[2][4], b[2][4];
            ldmA(a[0], AbL + ks*32,         SP, lane);
            ldmA(a[1], AbL + 16*SP + ks*32, SP, lane);
            ldmBt(b[0], BbH + ks*16*SV,      SV, lane);
            ldmBt(b[1], BbH + ks*16*SV + 32, SV, lane);
            #pragma unroll
            for (int mt = 0; mt < 2; mt++)
                #pragma unroll
                for (int nt = 0; nt < 4; nt++)
                    mma16816(o[mt][nt], a[mt], &b[nt >> 1][(nt & 1)*2]);
        }
    }
    __syncthreads();     // all warps done reading V smem before aliasing as sO

    // ---- epilogue: normalize, stage, coalesced store ----
    float* sO = (float*)(smc + OFF_VH);
    #pragma unroll
    for (int mt = 0; mt < 2; mt++) {
        int row0 = wm2*32 + mt*16 + g;
        float inv0 = sInv[row0], inv1 = sInv[row0 + 8];
        #pragma unroll
        for (int nt = 0; nt < 4; nt++) {
            int col = wn2*32 + nt*8 + qd*2;
            sO[row0*66 + col]       = o[mt][nt][0] * inv0;
            sO[row0*66 + col + 1]   = o[mt][nt][1] * inv0;
            sO[(row0+8)*66 + col]   = o[mt][nt][2] * inv1;
            sO[(row0+8)*66 + col+1] = o[mt][nt][3] * inv1;
        }
    }
    __syncthreads();

    float* ob = out + base;
    for (int i = tid; i < 4096; i += 256) {
        int r = i >> 5, p = i & 31;
        float2 val = *(const float2*)(sO + r*66 + p*2);
        *(float2*)(ob + r*64 + p*2) = val;
    }
}

// ---------------------------------------------------------------------------
extern "C" void kernel_launch(void* const* d_in, const int* in_sizes, int n_in,
                              void* d_out, int out_size) {
    const float* q  = (const float*)d_in[0];
    const float* k  = (const float*)d_in[1];
    const float* v  = (const float*)d_in[2];
    const float* Wk = (const float*)d_in[3];
    float* out = (float*)d_out;

    cudaFuncSetAttribute(k_attn, cudaFuncAttributeMaxDynamicSharedMemorySize, SMEM_TOT);

    k_bucket_sum    <<<BH*NBUCK, 256>>>(k);
    k_route_sinkhorn<<<BH, 1024>>>(Wk);
    k_kmix          <<<BH*16, 256>>>(k);
    k_attn          <<<BH*NBUCK, 256, SMEM_TOT>>>(q, v, out);
}

// round 6
// speedup vs baseline: 1.9083x; 1.1341x over previous
#include <cuda_runtime.h>
#include <cuda_bf16.h>
#include <cstdint>

#define BH      64
#define NH      16
#define NBUCK   32
#define BSZ     128
#define DIM     64
#define TOK     4096
#define ROW     (TOK*DIM)
#define BUCKF   (BSZ*DIM)

typedef unsigned long long u64;
typedef uint32_t u32;

__device__ float g_pl[BH*NBUCK*DIM];
__device__ float g_R [BH*NBUCK*NBUCK];
// K-mix output, bf16 hi/lo, layout [bh][bucket][token][d] as bf16x2 words
__device__ __align__(16) u32 g_kmh[BH*TOK*32];
__device__ __align__(16) u32 g_kml[BH*TOK*32];

// ---- f32x2 helpers ----------------------------------------------------------
__device__ __forceinline__ u64 pack2(float lo, float hi) {
    u64 r; asm("mov.b64 %0,{%1,%2};" : "=l"(r) : "f"(lo), "f"(hi)); return r;
}
__device__ __forceinline__ u64 dup2(float x) {
    u64 r; asm("mov.b64 %0,{%1,%1};" : "=l"(r) : "f"(x)); return r;
}
__device__ __forceinline__ void fma2(u64 &c, u64 a, u64 b) {
    asm("fma.rn.f32x2 %0,%1,%2,%0;" : "+l"(c) : "l"(a), "l"(b));
}
__device__ __forceinline__ float2 unpk(u64 p) {
    float2 f; asm("mov.b64 {%0,%1},%2;" : "=f"(f.x), "=f"(f.y) : "l"(p)); return f;
}

__device__ __forceinline__ u32 smem_u32(const void* p) {
    u32 a; asm("{ .reg .u64 t; cvta.to.shared.u64 t, %1; cvt.u32.u64 %0, t; }"
               : "=r"(a) : "l"(p)); return a;
}

// ---- warp MMA helpers -------------------------------------------------------
__device__ __forceinline__ void mma16816(float c[4], const u32 a[4], const u32* b) {
    asm volatile("mma.sync.aligned.m16n8k16.row.col.f32.bf16.bf16.f32 "
        "{%0,%1,%2,%3},{%4,%5,%6,%7},{%8,%9},{%0,%1,%2,%3};"
        : "+f"(c[0]), "+f"(c[1]), "+f"(c[2]), "+f"(c[3])
        : "r"(a[0]), "r"(a[1]), "r"(a[2]), "r"(a[3]), "r"(b[0]), "r"(b[1]));
}
__device__ __forceinline__ void ldmA(u32 a[4], u32 base, int stride, int lane) {
    int r = lane & 7, q = lane >> 3;
    u32 addr = base + (u32)((r + (q & 1) * 8) * stride + (q >> 1) * 16);
    asm volatile("ldmatrix.sync.aligned.m8n8.x4.shared.b16 {%0,%1,%2,%3}, [%4];"
                 : "=r"(a[0]), "=r"(a[1]), "=r"(a[2]), "=r"(a[3]) : "r"(addr));
}
__device__ __forceinline__ void ldmB(u32 b[4], u32 base, int stride, int lane) {
    int r = lane & 7, q = lane >> 3;
    u32 addr = base + (u32)((r + (q >> 1) * 8) * stride + (q & 1) * 16);
    asm volatile("ldmatrix.sync.aligned.m8n8.x4.shared.b16 {%0,%1,%2,%3}, [%4];"
                 : "=r"(b[0]), "=r"(b[1]), "=r"(b[2]), "=r"(b[3]) : "r"(addr));
}
__device__ __forceinline__ void ldmBt(u32 b[4], u32 base, int stride, int lane) {
    int r = lane & 7, q = lane >> 3;
    u32 addr = base + (u32)((r + (q & 1) * 8) * stride + (q >> 1) * 16);
    asm volatile("ldmatrix.sync.aligned.m8n8.x4.trans.shared.b16 {%0,%1,%2,%3}, [%4];"
                 : "=r"(b[0]), "=r"(b[1]), "=r"(b[2]), "=r"(b[3]) : "r"(addr));
}

// ---------------------------------------------------------------------------
// K1: pl[bh][i][d] = sum_s k[...]  (float4 loads, MLP=8)
// ---------------------------------------------------------------------------
__global__ __launch_bounds__(256) void k_bucket_sum(const float* __restrict__ k) {
    int bid = blockIdx.x;               // 2048
    int bh = bid >> 5, i = bid & 31;
    int t = threadIdx.x, c = t & 15, g = t >> 4;    // c: f4 col, g: 0..15
    const float4* kb4 = (const float4*)(k + (size_t)bh*ROW + (size_t)i*BUCKF);
    float4 s = make_float4(0.f, 0.f, 0.f, 0.f);
    #pragma unroll
    for (int ss = g; ss < BSZ; ss += 16) {
        float4 vv = kb4[ss*16 + c];
        s.x += vv.x; s.y += vv.y; s.z += vv.z; s.w += vv.w;
    }
    __shared__ float4 red[16][16];
    red[g][c] = s;
    __syncthreads();
    if (g == 0) {
        #pragma unroll
        for (int gg = 1; gg < 16; gg++) {
            float4 vv = red[gg][c];
            s.x += vv.x; s.y += vv.y; s.z += vv.z; s.w += vv.w;
        }
        ((float4*)(g_pl + (bh*NBUCK + i)*DIM))[c] = s;
    }
}

// ---------------------------------------------------------------------------
// JAX threefry2x32 (partitionable), key (0,42)
// ---------------------------------------------------------------------------
__device__ __forceinline__ uint32_t rotl32(uint32_t x, int r) {
    return (x << r) | (x >> (32 - r));
}
__device__ __forceinline__ uint32_t jax_bits32(uint32_t n) {
    const uint32_t k0 = 0u, k1 = 42u, k2 = 0u ^ 42u ^ 0x1BD11BDAu;
    uint32_t x0 = k0;
    uint32_t x1 = n + k1;
#define TF_R(r) { x0 += x1; x1 = rotl32(x1, r); x1 ^= x0; }
    TF_R(13) TF_R(15) TF_R(26) TF_R(6)   x0 += k1; x1 += k2 + 1u;
    TF_R(17) TF_R(29) TF_R(16) TF_R(24)  x0 += k2; x1 += k0 + 2u;
    TF_R(13) TF_R(15) TF_R(26) TF_R(6)   x0 += k0; x1 += k1 + 3u;
    TF_R(17) TF_R(29) TF_R(16) TF_R(24)  x0 += k1; x1 += k2 + 4u;
    TF_R(13) TF_R(15) TF_R(26) TF_R(6)   x0 += k2; x1 += k0 + 5u;
#undef TF_R
    return x0 ^ x1;
}

// ---------------------------------------------------------------------------
// K2: routing + gumbel + sinkhorn + exp
// ---------------------------------------------------------------------------
__global__ __launch_bounds__(1024) void k_route_sinkhorn(const float* __restrict__ Wk) {
    int bh = blockIdx.x;
    int h  = bh & (NH - 1);
    int tid = threadIdx.x;
    int i = tid >> 5, f = tid & 31;

    __shared__ float spl[NBUCK*DIM];
    __shared__ float sW [DIM*NBUCK];
    __shared__ float sM [NBUCK*33];

    spl[tid]        = g_pl[bh*(NBUCK*DIM) + tid];
    spl[tid + 1024] = g_pl[bh*(NBUCK*DIM) + tid + 1024];
    sW[tid]         = Wk[h*(DIM*NBUCK) + tid];
    sW[tid + 1024]  = Wk[h*(DIM*NBUCK) + tid + 1024];
    __syncthreads();

    float r = 0.f;
    #pragma unroll
    for (int d = 0; d < DIM; d++) r += spl[i*DIM + d] * sW[d*NBUCK + f];

    uint32_t n = (uint32_t)(bh*1024 + tid);
    uint32_t bits = jax_bits32(n);
    float u = __uint_as_float((bits >> 9) | 0x3f800000u) - 1.0f;
    float g = -logf(-logf(u + 1e-6f) + 1e-6f);
    r = (r + g) / 0.75f;

    for (int it = 0; it < 5; it++) {
        float m = r;
        #pragma unroll
        for (int o = 16; o >= 1; o >>= 1) m = fmaxf(m, __shfl_xor_sync(0xffffffffu, m, o));
        float s = __expf(r - m);
        #pragma unroll
        for (int o = 16; o >= 1; o >>= 1) s += __shfl_xor_sync(0xffffffffu, s, o);
        r = r - (__logf(s) + m);

        __syncthreads();
        sM[i*33 + f] = r;
        __syncthreads();
        float cm = -3.4e38f;
        #pragma unroll
        for (int ii = 0; ii < NBUCK; ii++) cm = fmaxf(cm, sM[ii*33 + f]);
        float cs = 0.f;
        #pragma unroll
        for (int ii = 0; ii < NBUCK; ii++) cs += __expf(sM[ii*33 + f] - cm);
        r = r - (__logf(cs) + cm);
    }
    g_R[bh*1024 + tid] = __expf(r);
}

// ---------------------------------------------------------------------------
// K3: Kmix = (R+I) @ K  -> bf16 hi/lo output.
// sAT transposed [j][ii] stride 36 so packed A-operands come from LDS.128.
// ---------------------------------------------------------------------------
__global__ __launch_bounds__(256) void k_kmix(const float* __restrict__ k) {
    int bid = blockIdx.x;               // 1024
    int bh = bid >> 4, c = bid & 15;
    int tid = threadIdx.x;

    __shared__ float sAT[NBUCK][36];    // [j][ii], row 144 B (16B-aligned rows)
    for (int idx = tid; idx < NBUCK*NBUCK; idx += 256) {
        int ii = idx >> 5, jj = idx & 31;
        sAT[jj][ii] = g_R[bh*1024 + idx] + ((ii == jj) ? 1.0f : 0.0f);
    }
    __syncthreads();

    const float2* kb2 = (const float2*)(k + (size_t)bh*ROW);
    int col2 = c*256 + tid;             // float2 index in [0,4096)
    int t = col2 >> 5, dd = col2 & 31;  // token, dim-pair

    u64 ax[16], ay[16];
    #pragma unroll
    for (int p = 0; p < 16; p++) { ax[p] = 0ull; ay[p] = 0ull; }

    #pragma unroll 2
    for (int j = 0; j < NBUCK; j++) {
        float2 kv = kb2[j*4096 + col2];
        u64 vx = dup2(kv.x), vy = dup2(kv.y);
        #pragma unroll
        for (int p4 = 0; p4 < 8; p4++) {
            float4 a4 = *(const float4*)&sAT[j][p4*4];
            u64 a01 = pack2(a4.x, a4.y), a23 = pack2(a4.z, a4.w);
            fma2(ax[2*p4],   a01, vx);
            fma2(ax[2*p4+1], a23, vx);
            fma2(ay[2*p4],   a01, vy);
            fma2(ay[2*p4+1], a23, vy);
        }
    }

    size_t ob = (size_t)bh * (TOK*32);
    #pragma unroll
    for (int p = 0; p < 16; p++) {
        float2 fx = unpk(ax[p]);   // (row 2p, 2p+1) at dim 2dd
        float2 fy = unpk(ay[p]);   // (row 2p, 2p+1) at dim 2dd+1
        // bucket row 2p
        __nv_bfloat162 h0 = __floats2bfloat162_rn(fx.x, fy.x);
        __nv_bfloat162 l0 = __floats2bfloat162_rn(fx.x - __bfloat162float(h0.x),
                                                  fy.x - __bfloat162float(h0.y));
        size_t o0 = ob + ((size_t)(2*p)*BSZ + t)*32 + dd;
        g_kmh[o0] = *(u32*)&h0;
        g_kml[o0] = *(u32*)&l0;
        // bucket row 2p+1
        __nv_bfloat162 h1 = __floats2bfloat162_rn(fx.y, fy.y);
        __nv_bfloat162 l1 = __floats2bfloat162_rn(fx.y - __bfloat162float(h1.x),
                                                  fy.y - __bfloat162float(h1.y));
        size_t o1 = ob + ((size_t)(2*p+1)*BSZ + t)*32 + dd;
        g_kmh[o1] = *(u32*)&h1;
        g_kml[o1] = *(u32*)&l1;
    }
}

// ---------------------------------------------------------------------------
// K4: bucket attention, ldmatrix + mma.sync bf16 hi/lo (fully merged loops).
// ---------------------------------------------------------------------------
#define OFF_QH 0
#define OFF_QL 18432
#define OFF_KH 36864
#define OFF_KL 55296
#define OFF_PH 0
#define OFF_PL 34816
#define OFF_VH 73728
#define OFF_VL 92160
#define OFF_PART 110592
#define OFF_SUM  111616
#define OFF_INV  112640
#define SMEM_TOT 113152
#define SQK 144
#define SP  272
#define SV  144

__global__ __launch_bounds__(256, 2) void k_attn(const float* __restrict__ q,
                                                 const float* __restrict__ v,
                                                 float* __restrict__ out) {
    extern __shared__ char smc[];
    u32 sb = smem_u32(smc);
    int tid = threadIdx.x, w = tid >> 5, lane = tid & 31;

    size_t base = (size_t)blockIdx.x * BUCKF;
    const float* qb = q + base;
    const float* vb = v + base;

    // ---- Q/V: load f32, split bf16 hi/lo.  K: direct u64 copy from kmix ----
    {
        const u64* kh8 = (const u64*)g_kmh + (size_t)blockIdx.x * 2048;
        const u64* kl8 = (const u64*)g_kml + (size_t)blockIdx.x * 2048;
        for (int i = tid; i < 2048; i += 256) {
            int r = i >> 4, cc = i & 15;
            u32 off = (u32)(r*SQK + cc*8);
            *(u64*)(smc + OFF_KH + off) = kh8[i];
            *(u64*)(smc + OFF_KL + off) = kl8[i];

            float4 qv = *(const float4*)(qb + r*64 + cc*4);
            qv.x *= 0.125f; qv.y *= 0.125f; qv.z *= 0.125f; qv.w *= 0.125f;
            __nv_bfloat162 qh0 = __floats2bfloat162_rn(qv.x, qv.y);
            __nv_bfloat162 qh1 = __floats2bfloat162_rn(qv.z, qv.w);
            __nv_bfloat162 ql0 = __floats2bfloat162_rn(qv.x - __bfloat162float(qh0.x),
                                                       qv.y - __bfloat162float(qh0.y));
            __nv_bfloat162 ql1 = __floats2bfloat162_rn(qv.z - __bfloat162float(qh1.x),
                                                       qv.w - __bfloat162float(qh1.y));
            *(u64*)(smc + OFF_QH + off) = ((u64)*(u32*)&qh1 << 32) | *(u32*)&qh0;
            *(u64*)(smc + OFF_QL + off) = ((u64)*(u32*)&ql1 << 32) | *(u32*)&ql0;

            float4 vv = *(const float4*)(vb + r*64 + cc*4);
            __nv_bfloat162 vh0 = __floats2bfloat162_rn(vv.x, vv.y);
            __nv_bfloat162 vh1 = __floats2bfloat162_rn(vv.z, vv.w);
            __nv_bfloat162 vl0 = __floats2bfloat162_rn(vv.x - __bfloat162float(vh0.x),
                                                       vv.y - __bfloat162float(vh0.y));
            __nv_bfloat162 vl1 = __floats2bfloat162_rn(vv.z - __bfloat162float(vh1.x),
                                                       vv.w - __bfloat162float(vh1.y));
            *(u64*)(smc + OFF_VH + off) = ((u64)*(u32*)&vh1 << 32) | *(u32*)&vh0;
            *(u64*)(smc + OFF_VL + off) = ((u64)*(u32*)&vl1 << 32) | *(u32*)&vl0;
        }
    }
    __syncthreads();

    // ---- GEMM1: S = Q K^T, fully merged (hh + lh + hl per ks) ----
    int wm = w & 3, wn = w >> 2;
    float acc[2][8][4];
    #pragma unroll
    for (int mt = 0; mt < 2; mt++)
        #pragma unroll
        for (int nt = 0; nt < 8; nt++)
            #pragma unroll
            for (int e = 0; e < 4; e++) acc[mt][nt][e] = 0.f;

    {
        u32 AbH = sb + OFF_QH + wm*32*SQK;
        u32 AbL = sb + OFF_QL + wm*32*SQK;
        u32 BbH = sb + OFF_KH + wn*64*SQK;
        u32 BbL = sb + OFF_KL + wn*64*SQK;
        #pragma unroll
        for (int ks = 0; ks < 4; ks++) {
            u32 ah[2][4], al[2][4], b[4][4];
            ldmA(ah[0], AbH + ks*32,          SQK, lane);
            ldmA(ah[1], AbH + 16*SQK + ks*32, SQK, lane);
            ldmA(al[0], AbL + ks*32,          SQK, lane);
            ldmA(al[1], AbL + 16*SQK + ks*32, SQK, lane);
            #pragma unroll
            for (int np = 0; np < 4; np++)
                ldmB(b[np], BbH + np*16*SQK + ks*32, SQK, lane);
            #pragma unroll
            for (int mt = 0; mt < 2; mt++)
                #pragma unroll
                for (int nt = 0; nt < 8; nt++)
                    mma16816(acc[mt][nt], ah[mt], &b[nt >> 1][(nt & 1)*2]);
            #pragma unroll
            for (int mt = 0; mt < 2; mt++)
                #pragma unroll
                for (int nt = 0; nt < 8; nt++)
                    mma16816(acc[mt][nt], al[mt], &b[nt >> 1][(nt & 1)*2]);
            #pragma unroll
            for (int np = 0; np < 4; np++)
                ldmB(b[np], BbL + np*16*SQK + ks*32, SQK, lane);
            #pragma unroll
            for (int mt = 0; mt < 2; mt++)
                #pragma unroll
                for (int nt = 0; nt < 8; nt++)
                    mma16816(acc[mt][nt], ah[mt], &b[nt >> 1][(nt & 1)*2]);
        }
    }

    // ---- softmax over key dim ----
    float* sPart = (float*)(smc + OFF_PART);
    float* sSum  = (float*)(smc + OFF_SUM);
    float* sInv  = (float*)(smc + OFF_INV);
    int g = lane >> 2, qd = lane & 3;

    #pragma unroll
    for (int mt = 0; mt < 2; mt++) {
        float m0 = -3.4e38f, m1 = -3.4e38f;
        #pragma unroll
        for (int nt = 0; nt < 8; nt++) {
            m0 = fmaxf(m0, fmaxf(acc[mt][nt][0], acc[mt][nt][1]));
            m1 = fmaxf(m1, fmaxf(acc[mt][nt][2], acc[mt][nt][3]));
        }
        m0 = fmaxf(m0, __shfl_xor_sync(0xffffffffu, m0, 1));
        m0 = fmaxf(m0, __shfl_xor_sync(0xffffffffu, m0, 2));
        m1 = fmaxf(m1, __shfl_xor_sync(0xffffffffu, m1, 1));
        m1 = fmaxf(m1, __shfl_xor_sync(0xffffffffu, m1, 2));
        if (qd == 0) {
            int row = wm*32 + mt*16 + g;
            sPart[wn*128 + row]     = m0;
            sPart[wn*128 + row + 8] = m1;
        }
    }
    __syncthreads();

    #pragma unroll
    for (int mt = 0; mt < 2; mt++) {
        int row = wm*32 + mt*16 + g;
        float gm0 = fmaxf(sPart[row],     sPart[128 + row]);
        float gm1 = fmaxf(sPart[row + 8], sPart[128 + row + 8]);
        float e0 = 0.f, e1 = 0.f;
        #pragma unroll
        for (int nt = 0; nt < 8; nt++) {
            acc[mt][nt][0] = __expf(acc[mt][nt][0] - gm0);
            acc[mt][nt][1] = __expf(acc[mt][nt][1] - gm0);
            acc[mt][nt][2] = __expf(acc[mt][nt][2] - gm1);
            acc[mt][nt][3] = __expf(acc[mt][nt][3] - gm1);
            e0 += acc[mt][nt][0] + acc[mt][nt][1];
            e1 += acc[mt][nt][2] + acc[mt][nt][3];
        }
        e0 += __shfl_xor_sync(0xffffffffu, e0, 1);
        e0 += __shfl_xor_sync(0xffffffffu, e0, 2);
        e1 += __shfl_xor_sync(0xffffffffu, e1, 1);
        e1 += __shfl_xor_sync(0xffffffffu, e1, 2);
        if (qd == 0) {
            sSum[wn*128 + row]     = e0;
            sSum[wn*128 + row + 8] = e1;
        }
    }

    // ---- convert unnormalized P to bf16 hi/lo into aliased Q/K smem ----
    #pragma unroll
    for (int mt = 0; mt < 2; mt++) {
        int row0 = wm*32 + mt*16 + g;
        #pragma unroll
        for (int nt = 0; nt < 8; nt++) {
            u32 cb = (u32)(wn*128 + nt*16 + qd*4);
            __nv_bfloat162 h0 = __floats2bfloat162_rn(acc[mt][nt][0], acc[mt][nt][1]);
            __nv_bfloat162 l0 = __floats2bfloat162_rn(acc[mt][nt][0] - __bfloat162float(h0.x),
                                                      acc[mt][nt][1] - __bfloat162float(h0.y));
            *(u32*)(smc + OFF_PH + row0*SP + cb) = *(u32*)&h0;
            *(u32*)(smc + OFF_PL + row0*SP + cb) = *(u32*)&l0;
            __nv_bfloat162 h1 = __floats2bfloat162_rn(acc[mt][nt][2], acc[mt][nt][3]);
            __nv_bfloat162 l1 = __floats2bfloat162_rn(acc[mt][nt][2] - __bfloat162float(h1.x),
                                                      acc[mt][nt][3] - __bfloat162float(h1.y));
            *(u32*)(smc + OFF_PH + (row0+8)*SP + cb) = *(u32*)&h1;
            *(u32*)(smc + OFF_PL + (row0+8)*SP + cb) = *(u32*)&l1;
        }
    }
    __syncthreads();

    if (wn == 0 && qd == 0) {
        #pragma unroll
        for (int mt = 0; mt < 2; mt++) {
            int row = wm*32 + mt*16 + g;
            sInv[row]     = 1.0f / (sSum[row]     + sSum[128 + row]);
            sInv[row + 8] = 1.0f / (sSum[row + 8] + sSum[128 + row + 8]);
        }
    }

    // ---- GEMM2: O = P V, fully merged per ks ----
    int wn2 = w & 1, wm2 = w >> 1;
    float o[2][4][4];
    #pragma unroll
    for (int mt = 0; mt < 2; mt++)
        #pragma unroll
        for (int nt = 0; nt < 4; nt++)
            #pragma unroll
            for (int e = 0; e < 4; e++) o[mt][nt][e] = 0.f;

    {
        u32 AbH = sb + OFF_PH + wm2*32*SP;
        u32 AbL = sb + OFF_PL + wm2*32*SP;
        u32 BbH = sb + OFF_VH + wn2*64;
        u32 BbL = sb + OFF_VL + wn2*64;
        #pragma unroll
        for (int ks = 0; ks < 8; ks++) {
            u32 ah[2][4], al[2][4], b[2][4];
            ldmA(ah[0], AbH + ks*32,         SP, lane);
            ldmA(ah[1], AbH + 16*SP + ks*32, SP, lane);
            ldmA(al[0], AbL + ks*32,         SP, lane);
            ldmA(al[1], AbL + 16*SP + ks*32, SP, lane);
            ldmBt(b[0], BbH + ks*16*SV,      SV, lane);
            ldmBt(b[1], BbH + ks*16*SV + 32, SV, lane);
            #pragma unroll
            for (int mt = 0; mt < 2; mt++)
                #pragma unroll
                for (int nt = 0; nt < 4; nt++)
                    mma16816(o[mt][nt], ah[mt], &b[nt >> 1][(nt & 1)*2]);
            #pragma unroll
            for (int mt = 0; mt < 2; mt++)
                #pragma unroll
                for (int nt = 0; nt < 4; nt++)
                    mma16816(o[mt][nt], al[mt], &b[nt >> 1][(nt & 1)*2]);
            ldmBt(b[0], BbL + ks*16*SV,      SV, lane);
            ldmBt(b[1], BbL + ks*16*SV + 32, SV, lane);
            #pragma unroll
            for (int mt = 0; mt < 2; mt++)
                #pragma unroll
                for (int nt = 0; nt < 4; nt++)
                    mma16816(o[mt][nt], ah[mt], &b[nt >> 1][(nt & 1)*2]);
        }
    }
    __syncthreads();     // all warps done reading V smem before aliasing as sO

    // ---- epilogue: normalize, stage, coalesced store ----
    float* sO = (float*)(smc + OFF_VH);
    #pragma unroll
    for (int mt = 0; mt < 2; mt++) {
        int row0 = wm2*32 + mt*16 + g;
        float inv0 = sInv[row0], inv1 = sInv[row0 + 8];
        #pragma unroll
        for (int nt = 0; nt < 4; nt++) {
            int col = wn2*32 + nt*8 + qd*2;
            sO[row0*66 + col]       = o[mt][nt][0] * inv0;
            sO[row0*66 + col + 1]   = o[mt][nt][1] * inv0;
            sO[(row0+8)*66 + col]   = o[mt][nt][2] * inv1;
            sO[(row0+8)*66 + col+1] = o[mt][nt][3] * inv1;
        }
    }
    __syncthreads();

    float* ob = out + base;
    for (int i = tid; i < 4096; i += 256) {
        int r = i >> 5, p = i & 31;
        float2 val = *(const float2*)(sO + r*66 + p*2);
        *(float2*)(ob + r*64 + p*2) = val;
    }
}

// ---------------------------------------------------------------------------
extern "C" void kernel_launch(void* const* d_in, const int* in_sizes, int n_in,
                              void* d_out, int out_size) {
    const float* q  = (const float*)d_in[0];
    const float* k  = (const float*)d_in[1];
    const float* v  = (const float*)d_in[2];
    const float* Wk = (const float*)d_in[3];
    float* out = (float*)d_out;

    cudaFuncSetAttribute(k_attn, cudaFuncAttributeMaxDynamicSharedMemorySize, SMEM_TOT);

    k_bucket_sum    <<<BH*NBUCK, 256>>>(k);
    k_route_sinkhorn<<<BH, 1024>>>(Wk);
    k_kmix          <<<BH*16, 256>>>(k);
    k_attn          <<<BH*NBUCK, 256, SMEM_TOT>>>(q, v, out);
}

// round 7
// speedup vs baseline: 2.0745x; 1.0871x over previous
#include <cuda_runtime.h>
#include <cuda_bf16.h>
#include <cstdint>

#define BH      64
#define NH      16
#define NBUCK   32
#define BSZ     128
#define DIM     64
#define TOK     4096
#define ROW     (TOK*DIM)
#define BUCKF   (BSZ*DIM)

typedef unsigned long long u64;
typedef uint32_t u32;

__device__ float g_pl[BH*NBUCK*DIM];
__device__ float g_R [BH*NBUCK*NBUCK];
// K-mix output, bf16 hi/lo, layout [bh][bucket][token][d] as bf16x2 words
__device__ __align__(16) u32 g_kmh[BH*TOK*32];
__device__ __align__(16) u32 g_kml[BH*TOK*32];

// ---- f32x2 helpers ----------------------------------------------------------
__device__ __forceinline__ u64 pack2(float lo, float hi) {
    u64 r; asm("mov.b64 %0,{%1,%2};" : "=l"(r) : "f"(lo), "f"(hi)); return r;
}
__device__ __forceinline__ u64 dup2(float x) {
    u64 r; asm("mov.b64 %0,{%1,%1};" : "=l"(r) : "f"(x)); return r;
}
__device__ __forceinline__ void fma2(u64 &c, u64 a, u64 b) {
    asm("fma.rn.f32x2 %0,%1,%2,%0;" : "+l"(c) : "l"(a), "l"(b));
}
__device__ __forceinline__ float2 unpk(u64 p) {
    float2 f; asm("mov.b64 {%0,%1},%2;" : "=f"(f.x), "=f"(f.y) : "l"(p)); return f;
}

__device__ __forceinline__ u32 smem_u32(const void* p) {
    u32 a; asm("{ .reg .u64 t; cvta.to.shared.u64 t, %1; cvt.u32.u64 %0, t; }"
               : "=r"(a) : "l"(p)); return a;
}
__device__ __forceinline__ u32 bf2(float a, float b) {
    __nv_bfloat162 h = __floats2bfloat162_rn(a, b);
    return *(u32*)&h;
}

// ---- warp MMA helpers -------------------------------------------------------
__device__ __forceinline__ void mma16816(float c[4], const u32 a[4], const u32* b) {
    asm volatile("mma.sync.aligned.m16n8k16.row.col.f32.bf16.bf16.f32 "
        "{%0,%1,%2,%3},{%4,%5,%6,%7},{%8,%9},{%0,%1,%2,%3};"
        : "+f"(c[0]), "+f"(c[1]), "+f"(c[2]), "+f"(c[3])
        : "r"(a[0]), "r"(a[1]), "r"(a[2]), "r"(a[3]), "r"(b[0]), "r"(b[1]));
}
__device__ __forceinline__ void ldmA(u32 a[4], u32 base, int stride, int lane) {
    int r = lane & 7, q = lane >> 3;
    u32 addr = base + (u32)((r + (q & 1) * 8) * stride + (q >> 1) * 16);
    asm volatile("ldmatrix.sync.aligned.m8n8.x4.shared.b16 {%0,%1,%2,%3}, [%4];"
                 : "=r"(a[0]), "=r"(a[1]), "=r"(a[2]), "=r"(a[3]) : "r"(addr));
}
__device__ __forceinline__ void ldmB(u32 b[4], u32 base, int stride, int lane) {
    int r = lane & 7, q = lane >> 3;
    u32 addr = base + (u32)((r + (q >> 1) * 8) * stride + (q & 1) * 16);
    asm volatile("ldmatrix.sync.aligned.m8n8.x4.shared.b16 {%0,%1,%2,%3}, [%4];"
                 : "=r"(b[0]), "=r"(b[1]), "=r"(b[2]), "=r"(b[3]) : "r"(addr));
}
__device__ __forceinline__ void ldmBt(u32 b[4], u32 base, int stride, int lane) {
    int r = lane & 7, q = lane >> 3;
    u32 addr = base + (u32)((r + (q & 1) * 8) * stride + (q >> 1) * 16);
    asm volatile("ldmatrix.sync.aligned.m8n8.x4.trans.shared.b16 {%0,%1,%2,%3}, [%4];"
                 : "=r"(b[0]), "=r"(b[1]), "=r"(b[2]), "=r"(b[3]) : "r"(addr));
}

// ---------------------------------------------------------------------------
// K1: pl[bh][i][d] = sum_s k[...]  (float4 loads)
// ---------------------------------------------------------------------------
__global__ __launch_bounds__(256) void k_bucket_sum(const float* __restrict__ k) {
    int bid = blockIdx.x;               // 2048
    int bh = bid >> 5, i = bid & 31;
    int t = threadIdx.x, c = t & 15, g = t >> 4;
    const float4* kb4 = (const float4*)(k + (size_t)bh*ROW + (size_t)i*BUCKF);
    float4 s = make_float4(0.f, 0.f, 0.f, 0.f);
    #pragma unroll
    for (int ss = g; ss < BSZ; ss += 16) {
        float4 vv = kb4[ss*16 + c];
        s.x += vv.x; s.y += vv.y; s.z += vv.z; s.w += vv.w;
    }
    __shared__ float4 red[16][16];
    red[g][c] = s;
    __syncthreads();
    if (g == 0) {
        #pragma unroll
        for (int gg = 1; gg < 16; gg++) {
            float4 vv = red[gg][c];
            s.x += vv.x; s.y += vv.y; s.z += vv.z; s.w += vv.w;
        }
        ((float4*)(g_pl + (bh*NBUCK + i)*DIM))[c] = s;
    }
}

// ---------------------------------------------------------------------------
// JAX threefry2x32 (partitionable), key (0,42)
// ---------------------------------------------------------------------------
__device__ __forceinline__ uint32_t rotl32(uint32_t x, int r) {
    return (x << r) | (x >> (32 - r));
}
__device__ __forceinline__ uint32_t jax_bits32(uint32_t n) {
    const uint32_t k0 = 0u, k1 = 42u, k2 = 0u ^ 42u ^ 0x1BD11BDAu;
    uint32_t x0 = k0;
    uint32_t x1 = n + k1;
#define TF_R(r) { x0 += x1; x1 = rotl32(x1, r); x1 ^= x0; }
    TF_R(13) TF_R(15) TF_R(26) TF_R(6)   x0 += k1; x1 += k2 + 1u;
    TF_R(17) TF_R(29) TF_R(16) TF_R(24)  x0 += k2; x1 += k0 + 2u;
    TF_R(13) TF_R(15) TF_R(26) TF_R(6)   x0 += k0; x1 += k1 + 3u;
    TF_R(17) TF_R(29) TF_R(16) TF_R(24)  x0 += k1; x1 += k2 + 4u;
    TF_R(13) TF_R(15) TF_R(26) TF_R(6)   x0 += k2; x1 += k0 + 5u;
#undef TF_R
    return x0 ^ x1;
}

// ---------------------------------------------------------------------------
// K2: routing + gumbel + sinkhorn + exp
// ---------------------------------------------------------------------------
__global__ __launch_bounds__(1024) void k_route_sinkhorn(const float* __restrict__ Wk) {
    int bh = blockIdx.x;
    int h  = bh & (NH - 1);
    int tid = threadIdx.x;
    int i = tid >> 5, f = tid & 31;

    __shared__ float spl[NBUCK*DIM];
    __shared__ float sW [DIM*NBUCK];
    __shared__ float sM [NBUCK*33];

    spl[tid]        = g_pl[bh*(NBUCK*DIM) + tid];
    spl[tid + 1024] = g_pl[bh*(NBUCK*DIM) + tid + 1024];
    sW[tid]         = Wk[h*(DIM*NBUCK) + tid];
    sW[tid + 1024]  = Wk[h*(DIM*NBUCK) + tid + 1024];
    __syncthreads();

    float r = 0.f;
    #pragma unroll
    for (int d = 0; d < DIM; d++) r += spl[i*DIM + d] * sW[d*NBUCK + f];

    uint32_t n = (uint32_t)(bh*1024 + tid);
    uint32_t bits = jax_bits32(n);
    float u = __uint_as_float((bits >> 9) | 0x3f800000u) - 1.0f;
    float g = -logf(-logf(u + 1e-6f) + 1e-6f);
    r = (r + g) / 0.75f;

    for (int it = 0; it < 5; it++) {
        float m = r;
        #pragma unroll
        for (int o = 16; o >= 1; o >>= 1) m = fmaxf(m, __shfl_xor_sync(0xffffffffu, m, o));
        float s = __expf(r - m);
        #pragma unroll
        for (int o = 16; o >= 1; o >>= 1) s += __shfl_xor_sync(0xffffffffu, s, o);
        r = r - (__logf(s) + m);

        __syncthreads();
        sM[i*33 + f] = r;
        __syncthreads();
        float cm = -3.4e38f;
        #pragma unroll
        for (int ii = 0; ii < NBUCK; ii++) cm = fmaxf(cm, sM[ii*33 + f]);
        float cs = 0.f;
        #pragma unroll
        for (int ii = 0; ii < NBUCK; ii++) cs += __expf(sM[ii*33 + f] - cm);
        r = r - (__logf(cs) + cm);
    }
    g_R[bh*1024 + tid] = __expf(r);
}

// ---------------------------------------------------------------------------
// K3: Kmix = (R+I) @ K  -> bf16 hi/lo output (sAT LDS.128 operands)
// ---------------------------------------------------------------------------
__global__ __launch_bounds__(256) void k_kmix(const float* __restrict__ k) {
    int bid = blockIdx.x;               // 1024
    int bh = bid >> 4, c = bid & 15;
    int tid = threadIdx.x;

    __shared__ float sAT[NBUCK][36];
    for (int idx = tid; idx < NBUCK*NBUCK; idx += 256) {
        int ii = idx >> 5, jj = idx & 31;
        sAT[jj][ii] = g_R[bh*1024 + idx] + ((ii == jj) ? 1.0f : 0.0f);
    }
    __syncthreads();

    const float2* kb2 = (const float2*)(k + (size_t)bh*ROW);
    int col2 = c*256 + tid;
    int t = col2 >> 5, dd = col2 & 31;

    u64 ax[16], ay[16];
    #pragma unroll
    for (int p = 0; p < 16; p++) { ax[p] = 0ull; ay[p] = 0ull; }

    #pragma unroll 2
    for (int j = 0; j < NBUCK; j++) {
        float2 kv = kb2[j*4096 + col2];
        u64 vx = dup2(kv.x), vy = dup2(kv.y);
        #pragma unroll
        for (int p4 = 0; p4 < 8; p4++) {
            float4 a4 = *(const float4*)&sAT[j][p4*4];
            u64 a01 = pack2(a4.x, a4.y), a23 = pack2(a4.z, a4.w);
            fma2(ax[2*p4],   a01, vx);
            fma2(ax[2*p4+1], a23, vx);
            fma2(ay[2*p4],   a01, vy);
            fma2(ay[2*p4+1], a23, vy);
        }
    }

    size_t ob = (size_t)bh * (TOK*32);
    #pragma unroll
    for (int p = 0; p < 16; p++) {
        float2 fx = unpk(ax[p]);
        float2 fy = unpk(ay[p]);
        __nv_bfloat162 h0 = __floats2bfloat162_rn(fx.x, fy.x);
        __nv_bfloat162 l0 = __floats2bfloat162_rn(fx.x - __bfloat162float(h0.x),
                                                  fy.x - __bfloat162float(h0.y));
        size_t o0 = ob + ((size_t)(2*p)*BSZ + t)*32 + dd;
        g_kmh[o0] = *(u32*)&h0;
        g_kml[o0] = *(u32*)&l0;
        __nv_bfloat162 h1 = __floats2bfloat162_rn(fx.y, fy.y);
        __nv_bfloat162 l1 = __floats2bfloat162_rn(fx.y - __bfloat162float(h1.x),
                                                  fy.y - __bfloat162float(h1.y));
        size_t o1 = ob + ((size_t)(2*p+1)*BSZ + t)*32 + dd;
        g_kmh[o1] = *(u32*)&h1;
        g_kml[o1] = *(u32*)&l1;
    }
}

// ---------------------------------------------------------------------------
// K4: bucket attention; GEMM2 uses register-resident P fragments (FA2 style).
// Warp (wm=w&3, wn=w>>2): GEMM1 rows wm*32, keys wn*64.
// GEMM2: same warp computes partial O[32 x 64] over its 64 keys, in two
// sequential 32-vcol halves; both warps of a row-pair dump f32 partials into
// the dead Q/K smem regions; cooperative final pass adds+normalizes+stores.
// SMEM: QH 0, QL 18432, KH 36864, KL 55296, VH 73728, VL 92160 (planes 18432)
//       partials: bufA(wn=0)@0 [4][32][72]f, bufB(wn=1)@36864
//       sPart@110592, sSum@111616, sInv@112640   total 113152
// ---------------------------------------------------------------------------
#define OFF_QH 0
#define OFF_QL 18432
#define OFF_KH 36864
#define OFF_KL 55296
#define OFF_VH 73728
#define OFF_VL 92160
#define OFF_BUFA 0
#define OFF_BUFB 36864
#define OFF_PART 110592
#define OFF_SUM  111616
#define OFF_INV  112640
#define SMEM_TOT 113152
#define SQK 144
#define SV  144
#define SRED 72     // f32 row stride of partial buffers

__global__ __launch_bounds__(256, 2) void k_attn(const float* __restrict__ q,
                                                 const float* __restrict__ v,
                                                 float* __restrict__ out) {
    extern __shared__ char smc[];
    u32 sb = smem_u32(smc);
    int tid = threadIdx.x, w = tid >> 5, lane = tid & 31;

    size_t base = (size_t)blockIdx.x * BUCKF;
    const float* qb = q + base;
    const float* vb = v + base;

    // ---- Q/V: load f32, split bf16 hi/lo.  K: direct u64 copy from kmix ----
    {
        const u64* kh8 = (const u64*)g_kmh + (size_t)blockIdx.x * 2048;
        const u64* kl8 = (const u64*)g_kml + (size_t)blockIdx.x * 2048;
        for (int i = tid; i < 2048; i += 256) {
            int r = i >> 4, cc = i & 15;
            u32 off = (u32)(r*SQK + cc*8);
            *(u64*)(smc + OFF_KH + off) = kh8[i];
            *(u64*)(smc + OFF_KL + off) = kl8[i];

            float4 qv = *(const float4*)(qb + r*64 + cc*4);
            qv.x *= 0.125f; qv.y *= 0.125f; qv.z *= 0.125f; qv.w *= 0.125f;
            u32 qh0 = bf2(qv.x, qv.y), qh1 = bf2(qv.z, qv.w);
            __nv_bfloat162 qhh0 = *(__nv_bfloat162*)&qh0;
            __nv_bfloat162 qhh1 = *(__nv_bfloat162*)&qh1;
            u32 ql0 = bf2(qv.x - __bfloat162float(qhh0.x), qv.y - __bfloat162float(qhh0.y));
            u32 ql1 = bf2(qv.z - __bfloat162float(qhh1.x), qv.w - __bfloat162float(qhh1.y));
            *(u64*)(smc + OFF_QH + off) = ((u64)qh1 << 32) | qh0;
            *(u64*)(smc + OFF_QL + off) = ((u64)ql1 << 32) | ql0;

            float4 vv = *(const float4*)(vb + r*64 + cc*4);
            u32 vh0 = bf2(vv.x, vv.y), vh1 = bf2(vv.z, vv.w);
            __nv_bfloat162 vhh0 = *(__nv_bfloat162*)&vh0;
            __nv_bfloat162 vhh1 = *(__nv_bfloat162*)&vh1;
            u32 vl0 = bf2(vv.x - __bfloat162float(vhh0.x), vv.y - __bfloat162float(vhh0.y));
            u32 vl1 = bf2(vv.z - __bfloat162float(vhh1.x), vv.w - __bfloat162float(vhh1.y));
            *(u64*)(smc + OFF_VH + off) = ((u64)vh1 << 32) | vh0;
            *(u64*)(smc + OFF_VL + off) = ((u64)vl1 << 32) | vl0;
        }
    }
    __syncthreads();

    // ---- GEMM1: S = Q K^T (hh + lh + hl per ks) ----
    int wm = w & 3, wn = w >> 2;
    float acc[2][8][4];
    #pragma unroll
    for (int mt = 0; mt < 2; mt++)
        #pragma unroll
        for (int nt = 0; nt < 8; nt++)
            #pragma unroll
            for (int e = 0; e < 4; e++) acc[mt][nt][e] = 0.f;

    {
        u32 AbH = sb + OFF_QH + wm*32*SQK;
        u32 AbL = sb + OFF_QL + wm*32*SQK;
        u32 BbH = sb + OFF_KH + wn*64*SQK;
        u32 BbL = sb + OFF_KL + wn*64*SQK;
        #pragma unroll
        for (int ks = 0; ks < 4; ks++) {
            u32 ah[2][4], al[2][4], b[4][4];
            ldmA(ah[0], AbH + ks*32,          SQK, lane);
            ldmA(ah[1], AbH + 16*SQK + ks*32, SQK, lane);
            ldmA(al[0], AbL + ks*32,          SQK, lane);
            ldmA(al[1], AbL + 16*SQK + ks*32, SQK, lane);
            #pragma unroll
            for (int np = 0; np < 4; np++)
                ldmB(b[np], BbH + np*16*SQK + ks*32, SQK, lane);
            #pragma unroll
            for (int mt = 0; mt < 2; mt++)
                #pragma unroll
                for (int nt = 0; nt < 8; nt++)
                    mma16816(acc[mt][nt], ah[mt], &b[nt >> 1][(nt & 1)*2]);
            #pragma unroll
            for (int mt = 0; mt < 2; mt++)
                #pragma unroll
                for (int nt = 0; nt < 8; nt++)
                    mma16816(acc[mt][nt], al[mt], &b[nt >> 1][(nt & 1)*2]);
            #pragma unroll
            for (int np = 0; np < 4; np++)
                ldmB(b[np], BbL + np*16*SQK + ks*32, SQK, lane);
            #pragma unroll
            for (int mt = 0; mt < 2; mt++)
                #pragma unroll
                for (int nt = 0; nt < 8; nt++)
                    mma16816(acc[mt][nt], ah[mt], &b[nt >> 1][(nt & 1)*2]);
        }
    }

    // ---- softmax over key dim ----
    float* sPart = (float*)(smc + OFF_PART);
    float* sSum  = (float*)(smc + OFF_SUM);
    float* sInv  = (float*)(smc + OFF_INV);
    int g = lane >> 2, qd = lane & 3;

    #pragma unroll
    for (int mt = 0; mt < 2; mt++) {
        float m0 = -3.4e38f, m1 = -3.4e38f;
        #pragma unroll
        for (int nt = 0; nt < 8; nt++) {
            m0 = fmaxf(m0, fmaxf(acc[mt][nt][0], acc[mt][nt][1]));
            m1 = fmaxf(m1, fmaxf(acc[mt][nt][2], acc[mt][nt][3]));
        }
        m0 = fmaxf(m0, __shfl_xor_sync(0xffffffffu, m0, 1));
        m0 = fmaxf(m0, __shfl_xor_sync(0xffffffffu, m0, 2));
        m1 = fmaxf(m1, __shfl_xor_sync(0xffffffffu, m1, 1));
        m1 = fmaxf(m1, __shfl_xor_sync(0xffffffffu, m1, 2));
        if (qd == 0) {
            int row = wm*32 + mt*16 + g;
            sPart[wn*128 + row]     = m0;
            sPart[wn*128 + row + 8] = m1;
        }
    }
    __syncthreads();

    #pragma unroll
    for (int mt = 0; mt < 2; mt++) {
        int row = wm*32 + mt*16 + g;
        float gm0 = fmaxf(sPart[row],     sPart[128 + row]);
        float gm1 = fmaxf(sPart[row + 8], sPart[128 + row + 8]);
        float e0 = 0.f, e1 = 0.f;
        #pragma unroll
        for (int nt = 0; nt < 8; nt++) {
            acc[mt][nt][0] = __expf(acc[mt][nt][0] - gm0);
            acc[mt][nt][1] = __expf(acc[mt][nt][1] - gm0);
            acc[mt][nt][2] = __expf(acc[mt][nt][2] - gm1);
            acc[mt][nt][3] = __expf(acc[mt][nt][3] - gm1);
            e0 += acc[mt][nt][0] + acc[mt][nt][1];
            e1 += acc[mt][nt][2] + acc[mt][nt][3];
        }
        e0 += __shfl_xor_sync(0xffffffffu, e0, 1);
        e0 += __shfl_xor_sync(0xffffffffu, e0, 2);
        e1 += __shfl_xor_sync(0xffffffffu, e1, 1);
        e1 += __shfl_xor_sync(0xffffffffu, e1, 2);
        if (qd == 0) {
            sSum[wn*128 + row]     = e0;
            sSum[wn*128 + row + 8] = e1;
        }
    }
    __syncthreads();

    if (wn == 0 && qd == 0) {
        #pragma unroll
        for (int mt = 0; mt < 2; mt++) {
            int row = wm*32 + mt*16 + g;
            sInv[row]     = 1.0f / (sSum[row]     + sSum[128 + row]);
            sInv[row + 8] = 1.0f / (sSum[row + 8] + sSum[128 + row + 8]);
        }
    }

    // ---- pack P accumulators into A fragments (registers; FA2 layout) ----
    // chunk t covers keys wn*64 + 16t; A[mt][t] = {c[2t]01, c[2t]23, c[2t+1]01, c[2t+1]23}
    u32 AH[2][4][4], AL[2][4][4];
    #pragma unroll
    for (int mt = 0; mt < 2; mt++)
        #pragma unroll
        for (int t = 0; t < 4; t++) {
            #pragma unroll
            for (int hp = 0; hp < 2; hp++) {       // nt = 2t + hp
                float p0 = acc[mt][2*t+hp][0], p1 = acc[mt][2*t+hp][1];
                float p2 = acc[mt][2*t+hp][2], p3 = acc[mt][2*t+hp][3];
                u32 h01 = bf2(p0, p1), h23 = bf2(p2, p3);
                __nv_bfloat162 hh01 = *(__nv_bfloat162*)&h01;
                __nv_bfloat162 hh23 = *(__nv_bfloat162*)&h23;
                AH[mt][t][2*hp]   = h01;
                AH[mt][t][2*hp+1] = h23;
                AL[mt][t][2*hp]   = bf2(p0 - __bfloat162float(hh01.x),
                                        p1 - __bfloat162float(hh01.y));
                AL[mt][t][2*hp+1] = bf2(p2 - __bfloat162float(hh23.x),
                                        p3 - __bfloat162float(hh23.y));
            }
        }

    // ---- GEMM2: partial O over this warp's 64 keys, two 32-vcol halves ----
    u32 bufb = sb + ((wn == 0) ? OFF_BUFA : OFF_BUFB);
    #pragma unroll
    for (int half = 0; half < 2; half++) {
        float o[2][4][4];
        #pragma unroll
        for (int mt = 0; mt < 2; mt++)
            #pragma unroll
            for (int nt = 0; nt < 4; nt++)
                #pragma unroll
                for (int e = 0; e < 4; e++) o[mt][nt][e] = 0.f;

        #pragma unroll
        for (int t = 0; t < 4; t++) {
            u32 vrow = sb + OFF_VH + (wn*64 + t*16)*SV + half*64;
            u32 b[2][4];
            ldmBt(b[0], vrow,      SV, lane);
            ldmBt(b[1], vrow + 32, SV, lane);
            #pragma unroll
            for (int mt = 0; mt < 2; mt++)
                #pragma unroll
                for (int nt = 0; nt < 4; nt++)
                    mma16816(o[mt][nt], AH[mt][t], &b[nt >> 1][(nt & 1)*2]);
            #pragma unroll
            for (int mt = 0; mt < 2; mt++)
                #pragma unroll
                for (int nt = 0; nt < 4; nt++)
                    mma16816(o[mt][nt], AL[mt][t], &b[nt >> 1][(nt & 1)*2]);
            u32 vrl = vrow + (OFF_VL - OFF_VH);
            ldmBt(b[0], vrl,      SV, lane);
            ldmBt(b[1], vrl + 32, SV, lane);
            #pragma unroll
            for (int mt = 0; mt < 2; mt++)
                #pragma unroll
                for (int nt = 0; nt < 4; nt++)
                    mma16816(o[mt][nt], AH[mt][t], &b[nt >> 1][(nt & 1)*2]);
        }

        // dump partial (f32) into buffer; rows wm*32+..., cols half*32+...
        #pragma unroll
        for (int mt = 0; mt < 2; mt++) {
            int row0 = wm*32 + mt*16 + g;
            #pragma unroll
            for (int nt = 0; nt < 4; nt++) {
                u32 cb = (u32)((half*32 + nt*8 + qd*2) * 4);
                *(float2*)(smc + (bufb - sb) + row0*(SRED*4) + cb) =
                    make_float2(o[mt][nt][0], o[mt][nt][1]);
                *(float2*)(smc + (bufb - sb) + (row0+8)*(SRED*4) + cb) =
                    make_float2(o[mt][nt][2], o[mt][nt][3]);
            }
        }
    }
    __syncthreads();

    // ---- final: add partials, normalize, coalesced store ----
    const float* bA = (const float*)(smc + OFF_BUFA);
    const float* bB = (const float*)(smc + OFF_BUFB);
    float* ob = out + base;
    for (int i = tid; i < 2048; i += 256) {          // float4 units
        int r = i >> 4, c4 = i & 15;
        float4 a4 = *(const float4*)(bA + r*SRED + c4*4);
        float4 b4 = *(const float4*)(bB + r*SRED + c4*4);
        float inv = sInv[r];
        float4 res = make_float4((a4.x + b4.x)*inv, (a4.y + b4.y)*inv,
                                 (a4.z + b4.z)*inv, (a4.w + b4.w)*inv);
        *(float4*)(ob + r*64 + c4*4) = res;
    }
}

// ---------------------------------------------------------------------------
extern "C" void kernel_launch(void* const* d_in, const int* in_sizes, int n_in,
                              void* d_out, int out_size) {
    const float* q  = (const float*)d_in[0];
    const float* k  = (const float*)d_in[1];
    const float* v  = (const float*)d_in[2];
    const float* Wk = (const float*)d_in[3];
    float* out = (float*)d_out;

    cudaFuncSetAttribute(k_attn, cudaFuncAttributeMaxDynamicSharedMemorySize, SMEM_TOT);

    k_bucket_sum    <<<BH*NBUCK, 256>>>(k);
    k_route_sinkhorn<<<BH, 1024>>>(Wk);
    k_kmix          <<<BH*16, 256>>>(k);
    k_attn          <<<BH*NBUCK, 256, SMEM_TOT>>>(q, v, out);
}

// round 8
// speedup vs baseline: 2.1423x; 1.0327x over previous
#include <cuda_runtime.h>
#include <cuda_bf16.h>
#include <cstdint>

#define BH      64
#define NH      16
#define NBUCK   32
#define BSZ     128
#define DIM     64
#define TOK     4096
#define ROW     (TOK*DIM)
#define BUCKF   (BSZ*DIM)

typedef unsigned long long u64;
typedef uint32_t u32;

__device__ float g_pl[BH*NBUCK*DIM];
__device__ float g_R [BH*NBUCK*NBUCK];
// K-mix output, bf16 hi/lo, layout [bh][bucket][token][d] as bf16x2 words
__device__ __align__(16) u32 g_kmh[BH*TOK*32];
__device__ __align__(16) u32 g_kml[BH*TOK*32];

// ---- f32x2 helpers ----------------------------------------------------------
__device__ __forceinline__ u64 pack2(float lo, float hi) {
    u64 r; asm("mov.b64 %0,{%1,%2};" : "=l"(r) : "f"(lo), "f"(hi)); return r;
}
__device__ __forceinline__ u64 dup2(float x) {
    u64 r; asm("mov.b64 %0,{%1,%1};" : "=l"(r) : "f"(x)); return r;
}
__device__ __forceinline__ void fma2(u64 &c, u64 a, u64 b) {
    asm("fma.rn.f32x2 %0,%1,%2,%0;" : "+l"(c) : "l"(a), "l"(b));
}
__device__ __forceinline__ float2 unpk(u64 p) {
    float2 f; asm("mov.b64 {%0,%1},%2;" : "=f"(f.x), "=f"(f.y) : "l"(p)); return f;
}

__device__ __forceinline__ u32 smem_u32(const void* p) {
    u32 a; asm("{ .reg .u64 t; cvta.to.shared.u64 t, %1; cvt.u32.u64 %0, t; }"
               : "=r"(a) : "l"(p)); return a;
}
__device__ __forceinline__ u32 bf2(float a, float b) {
    __nv_bfloat162 h = __floats2bfloat162_rn(a, b);
    return *(u32*)&h;
}
__device__ __forceinline__ void cp_async16(u32 saddr, const void* gaddr) {
    asm volatile("cp.async.cg.shared.global [%0], [%1], 16;"
                 :: "r"(saddr), "l"(gaddr) : "memory");
}
#define CP_COMMIT() asm volatile("cp.async.commit_group;" ::: "memory")
#define CP_WAIT0()  asm volatile("cp.async.wait_group 0;" ::: "memory")

// ---- warp MMA helpers -------------------------------------------------------
__device__ __forceinline__ void mma16816(float c[4], const u32 a[4], const u32* b) {
    asm volatile("mma.sync.aligned.m16n8k16.row.col.f32.bf16.bf16.f32 "
        "{%0,%1,%2,%3},{%4,%5,%6,%7},{%8,%9},{%0,%1,%2,%3};"
        : "+f"(c[0]), "+f"(c[1]), "+f"(c[2]), "+f"(c[3])
        : "r"(a[0]), "r"(a[1]), "r"(a[2]), "r"(a[3]), "r"(b[0]), "r"(b[1]));
}
__device__ __forceinline__ void ldmA(u32 a[4], u32 base, int stride, int lane) {
    int r = lane & 7, q = lane >> 3;
    u32 addr = base + (u32)((r + (q & 1) * 8) * stride + (q >> 1) * 16);
    asm volatile("ldmatrix.sync.aligned.m8n8.x4.shared.b16 {%0,%1,%2,%3}, [%4];"
                 : "=r"(a[0]), "=r"(a[1]), "=r"(a[2]), "=r"(a[3]) : "r"(addr));
}
__device__ __forceinline__ void ldmB(u32 b[4], u32 base, int stride, int lane) {
    int r = lane & 7, q = lane >> 3;
    u32 addr = base + (u32)((r + (q >> 1) * 8) * stride + (q & 1) * 16);
    asm volatile("ldmatrix.sync.aligned.m8n8.x4.shared.b16 {%0,%1,%2,%3}, [%4];"
                 : "=r"(b[0]), "=r"(b[1]), "=r"(b[2]), "=r"(b[3]) : "r"(addr));
}
__device__ __forceinline__ void ldmBt(u32 b[4], u32 base, int stride, int lane) {
    int r = lane & 7, q = lane >> 3;
    u32 addr = base + (u32)((r + (q & 1) * 8) * stride + (q >> 1) * 16);
    asm volatile("ldmatrix.sync.aligned.m8n8.x4.trans.shared.b16 {%0,%1,%2,%3}, [%4];"
                 : "=r"(b[0]), "=r"(b[1]), "=r"(b[2]), "=r"(b[3]) : "r"(addr));
}

// ---------------------------------------------------------------------------
// K1: pl[bh][i][d] = sum_s k[...]  (float4 loads)
// ---------------------------------------------------------------------------
__global__ __launch_bounds__(256) void k_bucket_sum(const float* __restrict__ k) {
    int bid = blockIdx.x;               // 2048
    int bh = bid >> 5, i = bid & 31;
    int t = threadIdx.x, c = t & 15, g = t >> 4;
    const float4* kb4 = (const float4*)(k + (size_t)bh*ROW + (size_t)i*BUCKF);
    float4 s = make_float4(0.f, 0.f, 0.f, 0.f);
    #pragma unroll
    for (int ss = g; ss < BSZ; ss += 16) {
        float4 vv = kb4[ss*16 + c];
        s.x += vv.x; s.y += vv.y; s.z += vv.z; s.w += vv.w;
    }
    __shared__ float4 red[16][16];
    red[g][c] = s;
    __syncthreads();
    if (g == 0) {
        #pragma unroll
        for (int gg = 1; gg < 16; gg++) {
            float4 vv = red[gg][c];
            s.x += vv.x; s.y += vv.y; s.z += vv.z; s.w += vv.w;
        }
        ((float4*)(g_pl + (bh*NBUCK + i)*DIM))[c] = s;
    }
}

// ---------------------------------------------------------------------------
// JAX threefry2x32 (partitionable), key (0,42)
// ---------------------------------------------------------------------------
__device__ __forceinline__ uint32_t rotl32(uint32_t x, int r) {
    return (x << r) | (x >> (32 - r));
}
__device__ __forceinline__ uint32_t jax_bits32(uint32_t n) {
    const uint32_t k0 = 0u, k1 = 42u, k2 = 0u ^ 42u ^ 0x1BD11BDAu;
    uint32_t x0 = k0;
    uint32_t x1 = n + k1;
#define TF_R(r) { x0 += x1; x1 = rotl32(x1, r); x1 ^= x0; }
    TF_R(13) TF_R(15) TF_R(26) TF_R(6)   x0 += k1; x1 += k2 + 1u;
    TF_R(17) TF_R(29) TF_R(16) TF_R(24)  x0 += k2; x1 += k0 + 2u;
    TF_R(13) TF_R(15) TF_R(26) TF_R(6)   x0 += k0; x1 += k1 + 3u;
    TF_R(17) TF_R(29) TF_R(16) TF_R(24)  x0 += k1; x1 += k2 + 4u;
    TF_R(13) TF_R(15) TF_R(26) TF_R(6)   x0 += k2; x1 += k0 + 5u;
#undef TF_R
    return x0 ^ x1;
}

// ---------------------------------------------------------------------------
// K2: routing + gumbel + sinkhorn + exp
// ---------------------------------------------------------------------------
__global__ __launch_bounds__(1024) void k_route_sinkhorn(const float* __restrict__ Wk) {
    int bh = blockIdx.x;
    int h  = bh & (NH - 1);
    int tid = threadIdx.x;
    int i = tid >> 5, f = tid & 31;

    __shared__ float spl[NBUCK*DIM];
    __shared__ float sW [DIM*NBUCK];
    __shared__ float sM [NBUCK*33];

    spl[tid]        = g_pl[bh*(NBUCK*DIM) + tid];
    spl[tid + 1024] = g_pl[bh*(NBUCK*DIM) + tid + 1024];
    sW[tid]         = Wk[h*(DIM*NBUCK) + tid];
    sW[tid + 1024]  = Wk[h*(DIM*NBUCK) + tid + 1024];
    __syncthreads();

    float r = 0.f;
    #pragma unroll
    for (int d = 0; d < DIM; d++) r += spl[i*DIM + d] * sW[d*NBUCK + f];

    uint32_t n = (uint32_t)(bh*1024 + tid);
    uint32_t bits = jax_bits32(n);
    float u = __uint_as_float((bits >> 9) | 0x3f800000u) - 1.0f;
    float g = -logf(-logf(u + 1e-6f) + 1e-6f);
    r = (r + g) / 0.75f;

    for (int it = 0; it < 5; it++) {
        float m = r;
        #pragma unroll
        for (int o = 16; o >= 1; o >>= 1) m = fmaxf(m, __shfl_xor_sync(0xffffffffu, m, o));
        float s = __expf(r - m);
        #pragma unroll
        for (int o = 16; o >= 1; o >>= 1) s += __shfl_xor_sync(0xffffffffu, s, o);
        r = r - (__logf(s) + m);

        __syncthreads();
        sM[i*33 + f] = r;
        __syncthreads();
        float cm = -3.4e38f;
        #pragma unroll
        for (int ii = 0; ii < NBUCK; ii++) cm = fmaxf(cm, sM[ii*33 + f]);
        float cs = 0.f;
        #pragma unroll
        for (int ii = 0; ii < NBUCK; ii++) cs += __expf(sM[ii*33 + f] - cm);
        r = r - (__logf(cs) + cm);
    }
    g_R[bh*1024 + tid] = __expf(r);
}

// ---------------------------------------------------------------------------
// K3: Kmix = (R+I) @ K  -> bf16 hi/lo output; pre-packed u64 sAT operands.
// ---------------------------------------------------------------------------
__global__ __launch_bounds__(256) void k_kmix(const float* __restrict__ k) {
    int bid = blockIdx.x;               // 1024
    int bh = bid >> 4, c = bid & 15;
    int tid = threadIdx.x;

    __shared__ __align__(16) u64 sAT[NBUCK][18];   // [j][p]: rows (2p,2p+1)
    for (int idx = tid; idx < NBUCK*16; idx += 256) {
        int j = idx >> 4, p = idx & 15;
        float a0 = g_R[bh*1024 + (2*p  )*32 + j] + ((2*p   == j) ? 1.0f : 0.0f);
        float a1 = g_R[bh*1024 + (2*p+1)*32 + j] + ((2*p+1 == j) ? 1.0f : 0.0f);
        sAT[j][p] = pack2(a0, a1);
    }
    __syncthreads();

    const float2* kb2 = (const float2*)(k + (size_t)bh*ROW);
    int col2 = c*256 + tid;
    int t = col2 >> 5, dd = col2 & 31;

    u64 ax[16], ay[16];
    #pragma unroll
    for (int p = 0; p < 16; p++) { ax[p] = 0ull; ay[p] = 0ull; }

    #pragma unroll 2
    for (int j = 0; j < NBUCK; j++) {
        float2 kv = kb2[j*4096 + col2];
        u64 vx = dup2(kv.x), vy = dup2(kv.y);
        #pragma unroll
        for (int p4 = 0; p4 < 8; p4++) {
            ulonglong2 aa = *(const ulonglong2*)&sAT[j][2*p4];
            fma2(ax[2*p4],   aa.x, vx);
            fma2(ax[2*p4+1], aa.y, vx);
            fma2(ay[2*p4],   aa.x, vy);
            fma2(ay[2*p4+1], aa.y, vy);
        }
    }

    size_t ob = (size_t)bh * (TOK*32);
    #pragma unroll
    for (int p = 0; p < 16; p++) {
        float2 fx = unpk(ax[p]);
        float2 fy = unpk(ay[p]);
        __nv_bfloat162 h0 = __floats2bfloat162_rn(fx.x, fy.x);
        __nv_bfloat162 l0 = __floats2bfloat162_rn(fx.x - __bfloat162float(h0.x),
                                                  fy.x - __bfloat162float(h0.y));
        size_t o0 = ob + ((size_t)(2*p)*BSZ + t)*32 + dd;
        g_kmh[o0] = *(u32*)&h0;
        g_kml[o0] = *(u32*)&l0;
        __nv_bfloat162 h1 = __floats2bfloat162_rn(fx.y, fy.y);
        __nv_bfloat162 l1 = __floats2bfloat162_rn(fx.y - __bfloat162float(h1.x),
                                                  fy.y - __bfloat162float(h1.y));
        size_t o1 = ob + ((size_t)(2*p+1)*BSZ + t)*32 + dd;
        g_kmh[o1] = *(u32*)&h1;
        g_kml[o1] = *(u32*)&l1;
    }
}

// ---------------------------------------------------------------------------
// K4: bucket attention; register-P GEMM2, no-max softmax, cp.async K copy.
// ---------------------------------------------------------------------------
#define OFF_QH 0
#define OFF_QL 18432
#define OFF_KH 36864
#define OFF_KL 55296
#define OFF_VH 73728
#define OFF_VL 92160
#define OFF_BUFA 0
#define OFF_BUFB 36864
#define OFF_SUM  111616
#define OFF_INV  112640
#define SMEM_TOT 113152
#define SQK 144
#define SV  144
#define SRED 72     // f32 row stride of partial buffers

__global__ __launch_bounds__(256, 2) void k_attn(const float* __restrict__ q,
                                                 const float* __restrict__ v,
                                                 float* __restrict__ out) {
    extern __shared__ char smc[];
    u32 sb = smem_u32(smc);
    int tid = threadIdx.x, w = tid >> 5, lane = tid & 31;

    size_t base = (size_t)blockIdx.x * BUCKF;
    const float* qb = q + base;
    const float* vb = v + base;

    // ---- K planes: cp.async 16B copies (overlap with Q/V conversion) ----
    {
        const uint4* kh16 = (const uint4*)g_kmh + (size_t)blockIdx.x * 1024;
        const uint4* kl16 = (const uint4*)g_kml + (size_t)blockIdx.x * 1024;
        for (int i = tid; i < 1024; i += 256) {
            int r = i >> 3, cc = i & 7;
            u32 soff = (u32)(r*SQK + cc*16);
            cp_async16(sb + OFF_KH + soff, kh16 + i);
            cp_async16(sb + OFF_KL + soff, kl16 + i);
        }
        CP_COMMIT();
    }

    // ---- Q/V: load f32, split bf16 hi/lo ----
    for (int i = tid; i < 2048; i += 256) {
        int r = i >> 4, cc = i & 15;
        u32 off = (u32)(r*SQK + cc*8);

        float4 qv = *(const float4*)(qb + r*64 + cc*4);
        qv.x *= 0.125f; qv.y *= 0.125f; qv.z *= 0.125f; qv.w *= 0.125f;
        u32 qh0 = bf2(qv.x, qv.y), qh1 = bf2(qv.z, qv.w);
        __nv_bfloat162 qhh0 = *(__nv_bfloat162*)&qh0;
        __nv_bfloat162 qhh1 = *(__nv_bfloat162*)&qh1;
        u32 ql0 = bf2(qv.x - __bfloat162float(qhh0.x), qv.y - __bfloat162float(qhh0.y));
        u32 ql1 = bf2(qv.z - __bfloat162float(qhh1.x), qv.w - __bfloat162float(qhh1.y));
        *(u64*)(smc + OFF_QH + off) = ((u64)qh1 << 32) | qh0;
        *(u64*)(smc + OFF_QL + off) = ((u64)ql1 << 32) | ql0;

        float4 vv = *(const float4*)(vb + r*64 + cc*4);
        u32 vh0 = bf2(vv.x, vv.y), vh1 = bf2(vv.z, vv.w);
        __nv_bfloat162 vhh0 = *(__nv_bfloat162*)&vh0;
        __nv_bfloat162 vhh1 = *(__nv_bfloat162*)&vh1;
        u32 vl0 = bf2(vv.x - __bfloat162float(vhh0.x), vv.y - __bfloat162float(vhh0.y));
        u32 vl1 = bf2(vv.z - __bfloat162float(vhh1.x), vv.w - __bfloat162float(vhh1.y));
        *(u64*)(smc + OFF_VH + off) = ((u64)vh1 << 32) | vh0;
        *(u64*)(smc + OFF_VL + off) = ((u64)vl1 << 32) | vl0;
    }
    CP_WAIT0();
    __syncthreads();

    // ---- GEMM1: S = Q K^T (hh + lh + hl per ks) ----
    int wm = w & 3, wn = w >> 2;
    float acc[2][8][4];
    #pragma unroll
    for (int mt = 0; mt < 2; mt++)
        #pragma unroll
        for (int nt = 0; nt < 8; nt++)
            #pragma unroll
            for (int e = 0; e < 4; e++) acc[mt][nt][e] = 0.f;

    {
        u32 AbH = sb + OFF_QH + wm*32*SQK;
        u32 AbL = sb + OFF_QL + wm*32*SQK;
        u32 BbH = sb + OFF_KH + wn*64*SQK;
        u32 BbL = sb + OFF_KL + wn*64*SQK;
        #pragma unroll
        for (int ks = 0; ks < 4; ks++) {
            u32 ah[2][4], al[2][4], b[4][4];
            ldmA(ah[0], AbH + ks*32,          SQK, lane);
            ldmA(ah[1], AbH + 16*SQK + ks*32, SQK, lane);
            ldmA(al[0], AbL + ks*32,          SQK, lane);
            ldmA(al[1], AbL + 16*SQK + ks*32, SQK, lane);
            #pragma unroll
            for (int np = 0; np < 4; np++)
                ldmB(b[np], BbH + np*16*SQK + ks*32, SQK, lane);
            #pragma unroll
            for (int mt = 0; mt < 2; mt++)
                #pragma unroll
                for (int nt = 0; nt < 8; nt++)
                    mma16816(acc[mt][nt], ah[mt], &b[nt >> 1][(nt & 1)*2]);
            #pragma unroll
            for (int mt = 0; mt < 2; mt++)
                #pragma unroll
                for (int nt = 0; nt < 8; nt++)
                    mma16816(acc[mt][nt], al[mt], &b[nt >> 1][(nt & 1)*2]);
            #pragma unroll
            for (int np = 0; np < 4; np++)
                ldmB(b[np], BbL + np*16*SQK + ks*32, SQK, lane);
            #pragma unroll
            for (int mt = 0; mt < 2; mt++)
                #pragma unroll
                for (int nt = 0; nt < 8; nt++)
                    mma16816(acc[mt][nt], ah[mt], &b[nt >> 1][(nt & 1)*2]);
        }
    }

    // ---- softmax (no max-shift: |S| bounded), sum over key dim ----
    float* sSum = (float*)(smc + OFF_SUM);
    float* sInv = (float*)(smc + OFF_INV);
    int g = lane >> 2, qd = lane & 3;

    #pragma unroll
    for (int mt = 0; mt < 2; mt++) {
        int row = wm*32 + mt*16 + g;
        float e0 = 0.f, e1 = 0.f;
        #pragma unroll
        for (int nt = 0; nt < 8; nt++) {
            acc[mt][nt][0] = __expf(acc[mt][nt][0]);
            acc[mt][nt][1] = __expf(acc[mt][nt][1]);
            acc[mt][nt][2] = __expf(acc[mt][nt][2]);
            acc[mt][nt][3] = __expf(acc[mt][nt][3]);
            e0 += acc[mt][nt][0] + acc[mt][nt][1];
            e1 += acc[mt][nt][2] + acc[mt][nt][3];
        }
        e0 += __shfl_xor_sync(0xffffffffu, e0, 1);
        e0 += __shfl_xor_sync(0xffffffffu, e0, 2);
        e1 += __shfl_xor_sync(0xffffffffu, e1, 1);
        e1 += __shfl_xor_sync(0xffffffffu, e1, 2);
        if (qd == 0) {
            sSum[wn*128 + row]     = e0;
            sSum[wn*128 + row + 8] = e1;
        }
    }
    __syncthreads();     // orders all GEMM1 smem reads before partial dumps

    if (wn == 0 && qd == 0) {
        #pragma unroll
        for (int mt = 0; mt < 2; mt++) {
            int row = wm*32 + mt*16 + g;
            sInv[row]     = 1.0f / (sSum[row]     + sSum[128 + row]);
            sInv[row + 8] = 1.0f / (sSum[row + 8] + sSum[128 + row + 8]);
        }
    }

    // ---- pack P accumulators into A fragments (registers) ----
    u32 AH[2][4][4], AL[2][4][4];
    #pragma unroll
    for (int mt = 0; mt < 2; mt++)
        #pragma unroll
        for (int t = 0; t < 4; t++) {
            #pragma unroll
            for (int hp = 0; hp < 2; hp++) {
                float p0 = acc[mt][2*t+hp][0], p1 = acc[mt][2*t+hp][1];
                float p2 = acc[mt][2*t+hp][2], p3 = acc[mt][2*t+hp][3];
                u32 h01 = bf2(p0, p1), h23 = bf2(p2, p3);
                __nv_bfloat162 hh01 = *(__nv_bfloat162*)&h01;
                __nv_bfloat162 hh23 = *(__nv_bfloat162*)&h23;
                AH[mt][t][2*hp]   = h01;
                AH[mt][t][2*hp+1] = h23;
                AL[mt][t][2*hp]   = bf2(p0 - __bfloat162float(hh01.x),
                                        p1 - __bfloat162float(hh01.y));
                AL[mt][t][2*hp+1] = bf2(p2 - __bfloat162float(hh23.x),
                                        p3 - __bfloat162float(hh23.y));
            }
        }

    // ---- GEMM2: partial O over this warp's 64 keys, two 32-vcol halves ----
    u32 bufb = sb + ((wn == 0) ? OFF_BUFA : OFF_BUFB);
    #pragma unroll
    for (int half = 0; half < 2; half++) {
        float o[2][4][4];
        #pragma unroll
        for (int mt = 0; mt < 2; mt++)
            #pragma unroll
            for (int nt = 0; nt < 4; nt++)
                #pragma unroll
                for (int e = 0; e < 4; e++) o[mt][nt][e] = 0.f;

        #pragma unroll
        for (int t = 0; t < 4; t++) {
            u32 vrow = sb + OFF_VH + (wn*64 + t*16)*SV + half*64;
            u32 b[2][4];
            ldmBt(b[0], vrow,      SV, lane);
            ldmBt(b[1], vrow + 32, SV, lane);
            #pragma unroll
            for (int mt = 0; mt < 2; mt++)
                #pragma unroll
                for (int nt = 0; nt < 4; nt++)
                    mma16816(o[mt][nt], AH[mt][t], &b[nt >> 1][(nt & 1)*2]);
            #pragma unroll
            for (int mt = 0; mt < 2; mt++)
                #pragma unroll
                for (int nt = 0; nt < 4; nt++)
                    mma16816(o[mt][nt], AL[mt][t], &b[nt >> 1][(nt & 1)*2]);
            u32 vrl = vrow + (OFF_VL - OFF_VH);
            ldmBt(b[0], vrl,      SV, lane);
            ldmBt(b[1], vrl + 32, SV, lane);
            #pragma unroll
            for (int mt = 0; mt < 2; mt++)
                #pragma unroll
                for (int nt = 0; nt < 4; nt++)
                    mma16816(o[mt][nt], AH[mt][t], &b[nt >> 1][(nt & 1)*2]);
        }

        #pragma unroll
        for (int mt = 0; mt < 2; mt++) {
            int row0 = wm*32 + mt*16 + g;
            #pragma unroll
            for (int nt = 0; nt < 4; nt++) {
                u32 cb = (u32)((half*32 + nt*8 + qd*2) * 4);
                *(float2*)(smc + (bufb - sb) + row0*(SRED*4) + cb) =
                    make_float2(o[mt][nt][0], o[mt][nt][1]);
                *(float2*)(smc + (bufb - sb) + (row0+8)*(SRED*4) + cb) =
                    make_float2(o[mt][nt][2], o[mt][nt][3]);
            }
        }
    }
    __syncthreads();

    // ---- final: add partials, normalize, coalesced store ----
    const float* bA = (const float*)(smc + OFF_BUFA);
    const float* bB = (const float*)(smc + OFF_BUFB);
    float* ob = out + base;
    for (int i = tid; i < 2048; i += 256) {
        int r = i >> 4, c4 = i & 15;
        float4 a4 = *(const float4*)(bA + r*SRED + c4*4);
        float4 b4 = *(const float4*)(bB + r*SRED + c4*4);
        float inv = sInv[r];
        float4 res = make_float4((a4.x + b4.x)*inv, (a4.y + b4.y)*inv,
                                 (a4.z + b4.z)*inv, (a4.w + b4.w)*inv);
        *(float4*)(ob + r*64 + c4*4) = res;
    }
}

// ---------------------------------------------------------------------------
extern "C" void kernel_launch(void* const* d_in, const int* in_sizes, int n_in,
                              void* d_out, int out_size) {
    const float* q  = (const float*)d_in[0];
    const float* k  = (const float*)d_in[1];
    const float* v  = (const float*)d_in[2];
    const float* Wk = (const float*)d_in[3];
    float* out = (float*)d_out;

    cudaFuncSetAttribute(k_attn, cudaFuncAttributeMaxDynamicSharedMemorySize, SMEM_TOT);

    k_bucket_sum    <<<BH*NBUCK, 256>>>(k);
    k_route_sinkhorn<<<BH, 1024>>>(Wk);
    k_kmix          <<<BH*16, 256>>>(k);
    k_attn          <<<BH*NBUCK, 256, SMEM_TOT>>>(q, v, out);
}

// round 9
// speedup vs baseline: 2.1758x; 1.0156x over previous
#include <cuda_runtime.h>
#include <cuda_bf16.h>
#include <cstdint>

#define BH      64
#define NH      16
#define NBUCK   32
#define BSZ     128
#define DIM     64
#define TOK     4096
#define ROW     (TOK*DIM)
#define BUCKF   (BSZ*DIM)

typedef unsigned long long u64;
typedef uint32_t u32;

__device__ float g_pl[BH*NBUCK*DIM];
__device__ float g_R [BH*NBUCK*NBUCK];
// K-mix output, bf16 hi/lo, layout [bh][bucket][token][d] as bf16x2 words
__device__ __align__(16) u32 g_kmh[BH*TOK*32];
__device__ __align__(16) u32 g_kml[BH*TOK*32];

// ---- f32x2 helpers ----------------------------------------------------------
__device__ __forceinline__ u64 pack2(float lo, float hi) {
    u64 r; asm("mov.b64 %0,{%1,%2};" : "=l"(r) : "f"(lo), "f"(hi)); return r;
}
__device__ __forceinline__ u64 dup2(float x) {
    u64 r; asm("mov.b64 %0,{%1,%1};" : "=l"(r) : "f"(x)); return r;
}
__device__ __forceinline__ void fma2(u64 &c, u64 a, u64 b) {
    asm("fma.rn.f32x2 %0,%1,%2,%0;" : "+l"(c) : "l"(a), "l"(b));
}
__device__ __forceinline__ float2 unpk(u64 p) {
    float2 f; asm("mov.b64 {%0,%1},%2;" : "=f"(f.x), "=f"(f.y) : "l"(p)); return f;
}

__device__ __forceinline__ u32 smem_u32(const void* p) {
    u32 a; asm("{ .reg .u64 t; cvta.to.shared.u64 t, %1; cvt.u32.u64 %0, t; }"
               : "=r"(a) : "l"(p)); return a;
}
__device__ __forceinline__ u32 bf2(float a, float b) {
    __nv_bfloat162 h = __floats2bfloat162_rn(a, b);
    return *(u32*)&h;
}
__device__ __forceinline__ void cp_async16(u32 saddr, const void* gaddr) {
    asm volatile("cp.async.cg.shared.global [%0], [%1], 16;"
                 :: "r"(saddr), "l"(gaddr) : "memory");
}
#define CP_COMMIT() asm volatile("cp.async.commit_group;" ::: "memory")
#define CP_WAIT0()  asm volatile("cp.async.wait_group 0;" ::: "memory")

// ---- warp MMA helpers -------------------------------------------------------
__device__ __forceinline__ void mma16816(float c[4], const u32 a[4], const u32* b) {
    asm volatile("mma.sync.aligned.m16n8k16.row.col.f32.bf16.bf16.f32 "
        "{%0,%1,%2,%3},{%4,%5,%6,%7},{%8,%9},{%0,%1,%2,%3};"
        : "+f"(c[0]), "+f"(c[1]), "+f"(c[2]), "+f"(c[3])
        : "r"(a[0]), "r"(a[1]), "r"(a[2]), "r"(a[3]), "r"(b[0]), "r"(b[1]));
}
__device__ __forceinline__ void ldmA(u32 a[4], u32 base, int stride, int lane) {
    int r = lane & 7, q = lane >> 3;
    u32 addr = base + (u32)((r + (q & 1) * 8) * stride + (q >> 1) * 16);
    asm volatile("ldmatrix.sync.aligned.m8n8.x4.shared.b16 {%0,%1,%2,%3}, [%4];"
                 : "=r"(a[0]), "=r"(a[1]), "=r"(a[2]), "=r"(a[3]) : "r"(addr));
}
__device__ __forceinline__ void ldmB(u32 b[4], u32 base, int stride, int lane) {
    int r = lane & 7, q = lane >> 3;
    u32 addr = base + (u32)((r + (q >> 1) * 8) * stride + (q & 1) * 16);
    asm volatile("ldmatrix.sync.aligned.m8n8.x4.shared.b16 {%0,%1,%2,%3}, [%4];"
                 : "=r"(b[0]), "=r"(b[1]), "=r"(b[2]), "=r"(b[3]) : "r"(addr));
}
__device__ __forceinline__ void ldmBt(u32 b[4], u32 base, int stride, int lane) {
    int r = lane & 7, q = lane >> 3;
    u32 addr = base + (u32)((r + (q & 1) * 8) * stride + (q >> 1) * 16);
    asm volatile("ldmatrix.sync.aligned.m8n8.x4.trans.shared.b16 {%0,%1,%2,%3}, [%4];"
                 : "=r"(b[0]), "=r"(b[1]), "=r"(b[2]), "=r"(b[3]) : "r"(addr));
}

// ---------------------------------------------------------------------------
// K1: pl[bh][i][d] = sum_s k[...]  (float4 loads)
// ---------------------------------------------------------------------------
__global__ __launch_bounds__(256) void k_bucket_sum(const float* __restrict__ k) {
    int bid = blockIdx.x;               // 2048
    int bh = bid >> 5, i = bid & 31;
    int t = threadIdx.x, c = t & 15, g = t >> 4;
    const float4* kb4 = (const float4*)(k + (size_t)bh*ROW + (size_t)i*BUCKF);
    float4 s = make_float4(0.f, 0.f, 0.f, 0.f);
    #pragma unroll
    for (int ss = g; ss < BSZ; ss += 16) {
        float4 vv = kb4[ss*16 + c];
        s.x += vv.x; s.y += vv.y; s.z += vv.z; s.w += vv.w;
    }
    __shared__ float4 red[16][16];
    red[g][c] = s;
    __syncthreads();
    if (g == 0) {
        #pragma unroll
        for (int gg = 1; gg < 16; gg++) {
            float4 vv = red[gg][c];
            s.x += vv.x; s.y += vv.y; s.z += vv.z; s.w += vv.w;
        }
        ((float4*)(g_pl + (bh*NBUCK + i)*DIM))[c] = s;
    }
}

// ---------------------------------------------------------------------------
// JAX threefry2x32 (partitionable), key (0,42)
// ---------------------------------------------------------------------------
__device__ __forceinline__ uint32_t rotl32(uint32_t x, int r) {
    return (x << r) | (x >> (32 - r));
}
__device__ __forceinline__ uint32_t jax_bits32(uint32_t n) {
    const uint32_t k0 = 0u, k1 = 42u, k2 = 0u ^ 42u ^ 0x1BD11BDAu;
    uint32_t x0 = k0;
    uint32_t x1 = n + k1;
#define TF_R(r) { x0 += x1; x1 = rotl32(x1, r); x1 ^= x0; }
    TF_R(13) TF_R(15) TF_R(26) TF_R(6)   x0 += k1; x1 += k2 + 1u;
    TF_R(17) TF_R(29) TF_R(16) TF_R(24)  x0 += k2; x1 += k0 + 2u;
    TF_R(13) TF_R(15) TF_R(26) TF_R(6)   x0 += k0; x1 += k1 + 3u;
    TF_R(17) TF_R(29) TF_R(16) TF_R(24)  x0 += k1; x1 += k2 + 4u;
    TF_R(13) TF_R(15) TF_R(26) TF_R(6)   x0 += k2; x1 += k0 + 5u;
#undef TF_R
    return x0 ^ x1;
}

// ---------------------------------------------------------------------------
// K2: routing + gumbel + sinkhorn + exp
// ---------------------------------------------------------------------------
__global__ __launch_bounds__(1024) void k_route_sinkhorn(const float* __restrict__ Wk) {
    int bh = blockIdx.x;
    int h  = bh & (NH - 1);
    int tid = threadIdx.x;
    int i = tid >> 5, f = tid & 31;

    __shared__ float spl[NBUCK*DIM];
    __shared__ float sW [DIM*NBUCK];
    __shared__ float sM [NBUCK*33];

    spl[tid]        = g_pl[bh*(NBUCK*DIM) + tid];
    spl[tid + 1024] = g_pl[bh*(NBUCK*DIM) + tid + 1024];
    sW[tid]         = Wk[h*(DIM*NBUCK) + tid];
    sW[tid + 1024]  = Wk[h*(DIM*NBUCK) + tid + 1024];
    __syncthreads();

    float r = 0.f;
    #pragma unroll
    for (int d = 0; d < DIM; d++) r += spl[i*DIM + d] * sW[d*NBUCK + f];

    uint32_t n = (uint32_t)(bh*1024 + tid);
    uint32_t bits = jax_bits32(n);
    float u = __uint_as_float((bits >> 9) | 0x3f800000u) - 1.0f;
    float g = -logf(-logf(u + 1e-6f) + 1e-6f);
    r = (r + g) / 0.75f;

    for (int it = 0; it < 5; it++) {
        float m = r;
        #pragma unroll
        for (int o = 16; o >= 1; o >>= 1) m = fmaxf(m, __shfl_xor_sync(0xffffffffu, m, o));
        float s = __expf(r - m);
        #pragma unroll
        for (int o = 16; o >= 1; o >>= 1) s += __shfl_xor_sync(0xffffffffu, s, o);
        r = r - (__logf(s) + m);

        __syncthreads();
        sM[i*33 + f] = r;
        __syncthreads();
        float cm = -3.4e38f;
        #pragma unroll
        for (int ii = 0; ii < NBUCK; ii++) cm = fmaxf(cm, sM[ii*33 + f]);
        float cs = 0.f;
        #pragma unroll
        for (int ii = 0; ii < NBUCK; ii++) cs += __expf(sM[ii*33 + f] - cm);
        r = r - (__logf(cs) + cm);
    }
    g_R[bh*1024 + tid] = __expf(r);
}

// ---------------------------------------------------------------------------
// K3: Kmix = (R+I) @ K  -> bf16 hi/lo output; pre-packed u64 sAT operands.
// ---------------------------------------------------------------------------
__global__ __launch_bounds__(256) void k_kmix(const float* __restrict__ k) {
    int bid = blockIdx.x;               // 1024
    int bh = bid >> 4, c = bid & 15;
    int tid = threadIdx.x;

    __shared__ __align__(16) u64 sAT[NBUCK][18];   // [j][p]: rows (2p,2p+1)
    for (int idx = tid; idx < NBUCK*16; idx += 256) {
        int j = idx >> 4, p = idx & 15;
        float a0 = g_R[bh*1024 + (2*p  )*32 + j] + ((2*p   == j) ? 1.0f : 0.0f);
        float a1 = g_R[bh*1024 + (2*p+1)*32 + j] + ((2*p+1 == j) ? 1.0f : 0.0f);
        sAT[j][p] = pack2(a0, a1);
    }
    __syncthreads();

    const float2* kb2 = (const float2*)(k + (size_t)bh*ROW);
    int col2 = c*256 + tid;
    int t = col2 >> 5, dd = col2 & 31;

    u64 ax[16], ay[16];
    #pragma unroll
    for (int p = 0; p < 16; p++) { ax[p] = 0ull; ay[p] = 0ull; }

    #pragma unroll 4
    for (int j = 0; j < NBUCK; j++) {
        float2 kv = kb2[j*4096 + col2];
        u64 vx = dup2(kv.x), vy = dup2(kv.y);
        #pragma unroll
        for (int p4 = 0; p4 < 8; p4++) {
            ulonglong2 aa = *(const ulonglong2*)&sAT[j][2*p4];
            fma2(ax[2*p4],   aa.x, vx);
            fma2(ax[2*p4+1], aa.y, vx);
            fma2(ay[2*p4],   aa.x, vy);
            fma2(ay[2*p4+1], aa.y, vy);
        }
    }

    size_t ob = (size_t)bh * (TOK*32);
    #pragma unroll
    for (int p = 0; p < 16; p++) {
        float2 fx = unpk(ax[p]);
        float2 fy = unpk(ay[p]);
        __nv_bfloat162 h0 = __floats2bfloat162_rn(fx.x, fy.x);
        __nv_bfloat162 l0 = __floats2bfloat162_rn(fx.x - __bfloat162float(h0.x),
                                                  fy.x - __bfloat162float(h0.y));
        size_t o0 = ob + ((size_t)(2*p)*BSZ + t)*32 + dd;
        g_kmh[o0] = *(u32*)&h0;
        g_kml[o0] = *(u32*)&l0;
        __nv_bfloat162 h1 = __floats2bfloat162_rn(fx.y, fy.y);
        __nv_bfloat162 l1 = __floats2bfloat162_rn(fx.y - __bfloat162float(h1.x),
                                                  fy.y - __bfloat162float(h1.y));
        size_t o1 = ob + ((size_t)(2*p+1)*BSZ + t)*32 + dd;
        g_kmh[o1] = *(u32*)&h1;
        g_kml[o1] = *(u32*)&l1;
    }
}

// ---------------------------------------------------------------------------
// K4: bucket attention; register-P GEMM2, deferred mid-barrier (skew hiding).
// Barrier plan:
//   sync0: after load head (Q/K/V smem ready)
//   sync1: AFTER GEMM2-half0 compute — orders all Q/K smem reads (GEMM1)
//          before partial dumps into the aliased Q/K-region buffers, and
//          makes sSum visible for the final pass.
//   sync2: after both partial dumps, before final add+normalize+store.
// ---------------------------------------------------------------------------
#define OFF_QH 0
#define OFF_QL 18432
#define OFF_KH 36864
#define OFF_KL 55296
#define OFF_VH 73728
#define OFF_VL 92160
#define OFF_BUFA 0
#define OFF_BUFB 36864
#define OFF_SUM  111616
#define SMEM_TOT 113152
#define SQK 144
#define SV  144
#define SRED 72     // f32 row stride of partial buffers

__global__ __launch_bounds__(256, 2) void k_attn(const float* __restrict__ q,
                                                 const float* __restrict__ v,
                                                 float* __restrict__ out) {
    extern __shared__ char smc[];
    u32 sb = smem_u32(smc);
    int tid = threadIdx.x, w = tid >> 5, lane = tid & 31;

    size_t base = (size_t)blockIdx.x * BUCKF;
    const float* qb = q + base;
    const float* vb = v + base;

    // ---- K planes: cp.async 16B copies (overlap with Q/V conversion) ----
    {
        const uint4* kh16 = (const uint4*)g_kmh + (size_t)blockIdx.x * 1024;
        const uint4* kl16 = (const uint4*)g_kml + (size_t)blockIdx.x * 1024;
        for (int i = tid; i < 1024; i += 256) {
            int r = i >> 3, cc = i & 7;
            u32 soff = (u32)(r*SQK + cc*16);
            cp_async16(sb + OFF_KH + soff, kh16 + i);
            cp_async16(sb + OFF_KL + soff, kl16 + i);
        }
        CP_COMMIT();
    }

    // ---- Q/V: load f32, split bf16 hi/lo ----
    for (int i = tid; i < 2048; i += 256) {
        int r = i >> 4, cc = i & 15;
        u32 off = (u32)(r*SQK + cc*8);

        float4 qv = *(const float4*)(qb + r*64 + cc*4);
        qv.x *= 0.125f; qv.y *= 0.125f; qv.z *= 0.125f; qv.w *= 0.125f;
        u32 qh0 = bf2(qv.x, qv.y), qh1 = bf2(qv.z, qv.w);
        __nv_bfloat162 qhh0 = *(__nv_bfloat162*)&qh0;
        __nv_bfloat162 qhh1 = *(__nv_bfloat162*)&qh1;
        u32 ql0 = bf2(qv.x - __bfloat162float(qhh0.x), qv.y - __bfloat162float(qhh0.y));
        u32 ql1 = bf2(qv.z - __bfloat162float(qhh1.x), qv.w - __bfloat162float(qhh1.y));
        *(u64*)(smc + OFF_QH + off) = ((u64)qh1 << 32) | qh0;
        *(u64*)(smc + OFF_QL + off) = ((u64)ql1 << 32) | ql0;

        float4 vv = *(const float4*)(vb + r*64 + cc*4);
        u32 vh0 = bf2(vv.x, vv.y), vh1 = bf2(vv.z, vv.w);
        __nv_bfloat162 vhh0 = *(__nv_bfloat162*)&vh0;
        __nv_bfloat162 vhh1 = *(__nv_bfloat162*)&vh1;
        u32 vl0 = bf2(vv.x - __bfloat162float(vhh0.x), vv.y - __bfloat162float(vhh0.y));
        u32 vl1 = bf2(vv.z - __bfloat162float(vhh1.x), vv.w - __bfloat162float(vhh1.y));
        *(u64*)(smc + OFF_VH + off) = ((u64)vh1 << 32) | vh0;
        *(u64*)(smc + OFF_VL + off) = ((u64)vl1 << 32) | vl0;
    }
    CP_WAIT0();
    __syncthreads();                                   // sync0

    // ---- GEMM1: S = Q K^T (hh + lh + hl per ks) ----
    int wm = w & 3, wn = w >> 2;
    float acc[2][8][4];
    #pragma unroll
    for (int mt = 0; mt < 2; mt++)
        #pragma unroll
        for (int nt = 0; nt < 8; nt++)
            #pragma unroll
            for (int e = 0; e < 4; e++) acc[mt][nt][e] = 0.f;

    {
        u32 AbH = sb + OFF_QH + wm*32*SQK;
        u32 AbL = sb + OFF_QL + wm*32*SQK;
        u32 BbH = sb + OFF_KH + wn*64*SQK;
        u32 BbL = sb + OFF_KL + wn*64*SQK;
        #pragma unroll
        for (int ks = 0; ks < 4; ks++) {
            u32 ah[2][4], al[2][4], b[4][4];
            ldmA(ah[0], AbH + ks*32,          SQK, lane);
            ldmA(ah[1], AbH + 16*SQK + ks*32, SQK, lane);
            ldmA(al[0], AbL + ks*32,          SQK, lane);
            ldmA(al[1], AbL + 16*SQK + ks*32, SQK, lane);
            #pragma unroll
            for (int np = 0; np < 4; np++)
                ldmB(b[np], BbH + np*16*SQK + ks*32, SQK, lane);
            #pragma unroll
            for (int mt = 0; mt < 2; mt++)
                #pragma unroll
                for (int nt = 0; nt < 8; nt++)
                    mma16816(acc[mt][nt], ah[mt], &b[nt >> 1][(nt & 1)*2]);
            #pragma unroll
            for (int mt = 0; mt < 2; mt++)
                #pragma unroll
                for (int nt = 0; nt < 8; nt++)
                    mma16816(acc[mt][nt], al[mt], &b[nt >> 1][(nt & 1)*2]);
            #pragma unroll
            for (int np = 0; np < 4; np++)
                ldmB(b[np], BbL + np*16*SQK + ks*32, SQK, lane);
            #pragma unroll
            for (int mt = 0; mt < 2; mt++)
                #pragma unroll
                for (int nt = 0; nt < 8; nt++)
                    mma16816(acc[mt][nt], ah[mt], &b[nt >> 1][(nt & 1)*2]);
        }
    }

    // ---- softmax (no max-shift: |S| bounded), per-warp-half sums ----
    float* sSum = (float*)(smc + OFF_SUM);
    int g = lane >> 2, qd = lane & 3;

    #pragma unroll
    for (int mt = 0; mt < 2; mt++) {
        int row = wm*32 + mt*16 + g;
        float e0 = 0.f, e1 = 0.f;
        #pragma unroll
        for (int nt = 0; nt < 8; nt++) {
            acc[mt][nt][0] = __expf(acc[mt][nt][0]);
            acc[mt][nt][1] = __expf(acc[mt][nt][1]);
            acc[mt][nt][2] = __expf(acc[mt][nt][2]);
            acc[mt][nt][3] = __expf(acc[mt][nt][3]);
            e0 += acc[mt][nt][0] + acc[mt][nt][1];
            e1 += acc[mt][nt][2] + acc[mt][nt][3];
        }
        e0 += __shfl_xor_sync(0xffffffffu, e0, 1);
        e0 += __shfl_xor_sync(0xffffffffu, e0, 2);
        e1 += __shfl_xor_sync(0xffffffffu, e1, 1);
        e1 += __shfl_xor_sync(0xffffffffu, e1, 2);
        if (qd == 0) {
            sSum[wn*128 + row]     = e0;
            sSum[wn*128 + row + 8] = e1;
        }
    }

    // ---- pack P accumulators into A fragments (registers) ----
    u32 AH[2][4][4], AL[2][4][4];
    #pragma unroll
    for (int mt = 0; mt < 2; mt++)
        #pragma unroll
        for (int t = 0; t < 4; t++) {
            #pragma unroll
            for (int hp = 0; hp < 2; hp++) {
                float p0 = acc[mt][2*t+hp][0], p1 = acc[mt][2*t+hp][1];
                float p2 = acc[mt][2*t+hp][2], p3 = acc[mt][2*t+hp][3];
                u32 h01 = bf2(p0, p1), h23 = bf2(p2, p3);
                __nv_bfloat162 hh01 = *(__nv_bfloat162*)&h01;
                __nv_bfloat162 hh23 = *(__nv_bfloat162*)&h23;
                AH[mt][t][2*hp]   = h01;
                AH[mt][t][2*hp+1] = h23;
                AL[mt][t][2*hp]   = bf2(p0 - __bfloat162float(hh01.x),
                                        p1 - __bfloat162float(hh01.y));
                AL[mt][t][2*hp+1] = bf2(p2 - __bfloat162float(hh23.x),
                                        p3 - __bfloat162float(hh23.y));
            }
        }

    // ---- GEMM2 half0 compute (V reads only; runs BEFORE the barrier) ----
    u32 bufoff = (wn == 0) ? OFF_BUFA : OFF_BUFB;
    float o0[2][4][4];
    #pragma unroll
    for (int mt = 0; mt < 2; mt++)
        #pragma unroll
        for (int nt = 0; nt < 4; nt++)
            #pragma unroll
            for (int e = 0; e < 4; e++) o0[mt][nt][e] = 0.f;

    #pragma unroll
    for (int t = 0; t < 4; t++) {
        u32 vrow = sb + OFF_VH + (wn*64 + t*16)*SV;
        u32 b[2][4];
        ldmBt(b[0], vrow,      SV, lane);
        ldmBt(b[1], vrow + 32, SV, lane);
        #pragma unroll
        for (int mt = 0; mt < 2; mt++)
            #pragma unroll
            for (int nt = 0; nt < 4; nt++)
                mma16816(o0[mt][nt], AH[mt][t], &b[nt >> 1][(nt & 1)*2]);
        #pragma unroll
        for (int mt = 0; mt < 2; mt++)
            #pragma unroll
            for (int nt = 0; nt < 4; nt++)
                mma16816(o0[mt][nt], AL[mt][t], &b[nt >> 1][(nt & 1)*2]);
        u32 vrl = vrow + (OFF_VL - OFF_VH);
        ldmBt(b[0], vrl,      SV, lane);
        ldmBt(b[1], vrl + 32, SV, lane);
        #pragma unroll
        for (int mt = 0; mt < 2; mt++)
            #pragma unroll
            for (int nt = 0; nt < 4; nt++)
                mma16816(o0[mt][nt], AH[mt][t], &b[nt >> 1][(nt & 1)*2]);
    }

    __syncthreads();                                   // sync1

    // ---- dump half0 partials into aliased Q/K-region buffer ----
    #pragma unroll
    for (int mt = 0; mt < 2; mt++) {
        int row0 = wm*32 + mt*16 + g;
        #pragma unroll
        for (int nt = 0; nt < 4; nt++) {
            u32 cb = (u32)((nt*8 + qd*2) * 4);
            *(float2*)(smc + bufoff + row0*(SRED*4) + cb) =
                make_float2(o0[mt][nt][0], o0[mt][nt][1]);
            *(float2*)(smc + bufoff + (row0+8)*(SRED*4) + cb) =
                make_float2(o0[mt][nt][2], o0[mt][nt][3]);
        }
    }

    // ---- GEMM2 half1 compute + dump ----
    {
        float o1[2][4][4];
        #pragma unroll
        for (int mt = 0; mt < 2; mt++)
            #pragma unroll
            for (int nt = 0; nt < 4; nt++)
                #pragma unroll
                for (int e = 0; e < 4; e++) o1[mt][nt][e] = 0.f;

        #pragma unroll
        for (int t = 0; t < 4; t++) {
            u32 vrow = sb + OFF_VH + (wn*64 + t*16)*SV + 64;
            u32 b[2][4];
            ldmBt(b[0], vrow,      SV, lane);
            ldmBt(b[1], vrow + 32, SV, lane);
            #pragma unroll
            for (int mt = 0; mt < 2; mt++)
                #pragma unroll
                for (int nt = 0; nt < 4; nt++)
                    mma16816(o1[mt][nt], AH[mt][t], &b[nt >> 1][(nt & 1)*2]);
            #pragma unroll
            for (int mt = 0; mt < 2; mt++)
                #pragma unroll
                for (int nt = 0; nt < 4; nt++)
                    mma16816(o1[mt][nt], AL[mt][t], &b[nt >> 1][(nt & 1)*2]);
            u32 vrl = vrow + (OFF_VL - OFF_VH);
            ldmBt(b[0], vrl,      SV, lane);
            ldmBt(b[1], vrl + 32, SV, lane);
            #pragma unroll
            for (int mt = 0; mt < 2; mt++)
                #pragma unroll
                for (int nt = 0; nt < 4; nt++)
                    mma16816(o1[mt][nt], AH[mt][t], &b[nt >> 1][(nt & 1)*2]);
        }

        #pragma unroll
        for (int mt = 0; mt < 2; mt++) {
            int row0 = wm*32 + mt*16 + g;
            #pragma unroll
            for (int nt = 0; nt < 4; nt++) {
                u32 cb = (u32)((32 + nt*8 + qd*2) * 4);
                *(float2*)(smc + bufoff + row0*(SRED*4) + cb) =
                    make_float2(o1[mt][nt][0], o1[mt][nt][1]);
                *(float2*)(smc + bufoff + (row0+8)*(SRED*4) + cb) =
                    make_float2(o1[mt][nt][2], o1[mt][nt][3]);
            }
        }
    }
    __syncthreads();                                   // sync2

    // ---- final: add partials, normalize (per-thread inv), store ----
    const float* bA = (const float*)(smc + OFF_BUFA);
    const float* bB = (const float*)(smc + OFF_BUFB);
    float* ob = out + base;
    for (int i = tid; i < 2048; i += 256) {
        int r = i >> 4, c4 = i & 15;
        float4 a4 = *(const float4*)(bA + r*SRED + c4*4);
        float4 b4 = *(const float4*)(bB + r*SRED + c4*4);
        float inv = 1.0f / (sSum[r] + sSum[128 + r]);
        float4 res = make_float4((a4.x + b4.x)*inv, (a4.y + b4.y)*inv,
                                 (a4.z + b4.z)*inv, (a4.w + b4.w)*inv);
        *(float4*)(ob + r*64 + c4*4) = res;
    }
}

// ---------------------------------------------------------------------------
extern "C" void kernel_launch(void* const* d_in, const int* in_sizes, int n_in,
                              void* d_out, int out_size) {
    const float* q  = (const float*)d_in[0];
    const float* k  = (const float*)d_in[1];
    const float* v  = (const float*)d_in[2];
    const float* Wk = (const float*)d_in[3];
    float* out = (float*)d_out;

    cudaFuncSetAttribute(k_attn, cudaFuncAttributeMaxDynamicSharedMemorySize, SMEM_TOT);

    k_bucket_sum    <<<BH*NBUCK, 256>>>(k);
    k_route_sinkhorn<<<BH, 1024>>>(Wk);
    k_kmix          <<<BH*16, 256>>>(k);
    k_attn          <<<BH*NBUCK, 256, SMEM_TOT>>>(q, v, out);
}